// round 14
// baseline (speedup 1.0000x reference)
#include <cuda_runtime.h>
#include <cuda_fp16.h>
#include <math.h>
#include <stdint.h>

// Problem constants
#define DIMC   768
#define NHEADS 12
#define HD     64
#define BATCH  16
#define SEQ    596
#define ROWS   (BATCH*SEQ)      // 9536
#define HBATCH (BATCH/2)
#define HROWS  (HBATCH*SEQ)     // 4768
#define QKVC   2304
#define HIDDEN 3072
#define CLSK   20

// ---------------- scratch ---------------------------------------------------------
__device__ __half g_h1h [ROWS*DIMC];
__device__ __half g_qkvh[ROWS*QKVC];
__device__ __half g_och [ROWS*DIMC];
__device__ __half g_mlph[ROWS*HIDDEN];
__device__ float  g_x2  [ROWS*DIMC];
__device__ __half g_qkvwh[QKVC*DIMC];
__device__ __half g_projwh[DIMC*DIMC];
__device__ __half g_fc1wh[HIDDEN*DIMC];
__device__ __half g_fc2wh[DIMC*HIDDEN];

// ---------------- fp32 -> fp16, vectorized ----------------------------------------
__global__ void f2h4(const float4* __restrict__ a, __half2* __restrict__ o, int n4) {
    int i = blockIdx.x * 256 + threadIdx.x;
    if (i < n4) {
        float4 v = a[i];
        o[2 * i]     = __floats2half2_rn(v.x, v.y);
        o[2 * i + 1] = __floats2half2_rn(v.z, v.w);
    }
}

// ---------------- LayerNorm: 192 thr/row, single pass, register-cached -------------
__global__ __launch_bounds__(192)
void ln_kernel(const float* __restrict__ x,
               const float* __restrict__ g,
               const float* __restrict__ b,
               __half* __restrict__ out) {
    int row = blockIdx.x;
    int t = threadIdx.x;
    const float4* xr = (const float4*)(x + (long long)row * DIMC);
    float4 v = xr[t];

    float s  = v.x + v.y + v.z + v.w;
    float s2 = v.x * v.x + v.y * v.y + v.z * v.z + v.w * v.w;
    #pragma unroll
    for (int o = 16; o; o >>= 1) {
        s  += __shfl_xor_sync(0xffffffffu, s,  o);
        s2 += __shfl_xor_sync(0xffffffffu, s2, o);
    }
    __shared__ float rs[6], rs2[6];
    int wid = t >> 5, lid = t & 31;
    if (lid == 0) { rs[wid] = s; rs2[wid] = s2; }
    __syncthreads();
    if (t < 32) {
        float a  = (t < 6) ? rs[t]  : 0.f;
        float a2 = (t < 6) ? rs2[t] : 0.f;
        #pragma unroll
        for (int o = 4; o; o >>= 1) {
            a  += __shfl_xor_sync(0xffffffffu, a,  o);
            a2 += __shfl_xor_sync(0xffffffffu, a2, o);
        }
        if (t == 0) { rs[0] = a; rs2[0] = a2; }
    }
    __syncthreads();
    float mean = rs[0] * (1.0f / DIMC);
    float var  = rs2[0] * (1.0f / DIMC) - mean * mean;
    float inv  = rsqrtf(var + 1e-5f);

    float4 gg = *(const float4*)(g + t * 4);
    float4 bb = *(const float4*)(b + t * 4);
    float o0 = (v.x - mean) * inv * gg.x + bb.x;
    float o1 = (v.y - mean) * inv * gg.y + bb.y;
    float o2 = (v.z - mean) * inv * gg.z + bb.z;
    float o3 = (v.w - mean) * inv * gg.w + bb.w;
    __half2 h01 = __floats2half2_rn(o0, o1);
    __half2 h23 = __floats2half2_rn(o2, o3);
    uint2 pk = make_uint2(*(uint32_t*)&h01, *(uint32_t*)&h23);
    *(uint2*)(out + (long long)row * DIMC + t * 4) = pk;
}

// ---------------- shared helpers ---------------------------------------------------
#define SROWB 144

__device__ __forceinline__ void mma16(float* c, const uint32_t* a, const uint32_t* b) {
    asm volatile(
        "mma.sync.aligned.m16n8k16.row.col.f32.f16.f16.f32 "
        "{%0,%1,%2,%3}, {%4,%5,%6,%7}, {%8,%9}, {%0,%1,%2,%3};"
        : "+f"(c[0]), "+f"(c[1]), "+f"(c[2]), "+f"(c[3])
        : "r"(a[0]), "r"(a[1]), "r"(a[2]), "r"(a[3]), "r"(b[0]), "r"(b[1]));
}
__device__ __forceinline__ void cpa16(uint32_t dst, const void* src, bool pred) {
    unsigned ssz = pred ? 16u : 0u;
    asm volatile("cp.async.cg.shared.global [%0], [%1], 16, %2;"
                 :: "r"(dst), "l"(src), "r"(ssz));
}
__device__ __forceinline__ void cp_commit() { asm volatile("cp.async.commit_group;"); }

__device__ __forceinline__ void ldmA(uint32_t* a, uint32_t base, int m0, int kb, int lane) {
    uint32_t addr = base + (uint32_t)(m0 + (lane & 15)) * SROWB
                  + (uint32_t)(kb + (lane >> 4) * 8) * 2;
    asm volatile("ldmatrix.sync.aligned.m8n8.x4.shared.b16 {%0,%1,%2,%3}, [%4];"
                 : "=r"(a[0]), "=r"(a[1]), "=r"(a[2]), "=r"(a[3]) : "r"(addr));
}
__device__ __forceinline__ void ldmB2(uint32_t* b, uint32_t base, int n0, int kb, int lane) {
    uint32_t addr = base + (uint32_t)(n0 + (lane & 7) + ((lane >> 4) * 8)) * SROWB
                  + (uint32_t)(kb + ((lane >> 3) & 1) * 8) * 2;
    asm volatile("ldmatrix.sync.aligned.m8n8.x4.shared.b16 {%0,%1,%2,%3}, [%4];"
                 : "=r"(b[0]), "=r"(b[1]), "=r"(b[2]), "=r"(b[3]) : "r"(addr));
}
__device__ __forceinline__ void ldm4(uint32_t* r, uint32_t addr) {
    asm volatile("ldmatrix.sync.aligned.m8n8.x4.shared.b16 {%0,%1,%2,%3}, [%4];"
                 : "=r"(r[0]), "=r"(r[1]), "=r"(r[2]), "=r"(r[3]) : "r"(addr));
}
__device__ __forceinline__ void ldm4t(uint32_t* r, uint32_t addr) {
    asm volatile("ldmatrix.sync.aligned.m8n8.x4.trans.shared.b16 {%0,%1,%2,%3}, [%4];"
                 : "=r"(r[0]), "=r"(r[1]), "=r"(r[2]), "=r"(r[3]) : "r"(addr));
}

// exact GELU: x * Phi(x)
__device__ __forceinline__ float gelu_exact(float x) {
    return x * normcdff(x);
}

// ---------------- fused attention: QK^T -> split softmax -> AV ---------------------
#define QS 64
#define SRS 2560
#define KV_STG (128*SROWB)
#define SM_Q  0
#define SM_KV 9216
#define SM_S  46080
#define ATTN_SMEM (SM_S + QS*SRS)     // 209920

__global__ __launch_bounds__(256, 1)
void attn_fused(const __half* __restrict__ qkvh,
                float* __restrict__ out_w,
                __half* __restrict__ och) {
    extern __shared__ __align__(16) char sh[];
    uint32_t shb = (uint32_t)__cvta_generic_to_shared(sh);

    int z = blockIdx.y;
    int b = z / NHEADS, h = z % NHEADS;
    int q0 = blockIdx.x * QS;
    int tid = threadIdx.x, warp = tid >> 5, lane = tid & 31;
    int wm = warp >> 1, wn = warp & 1;
    int group = lane >> 2, tg = lane & 3;

    const __half* Qg = qkvh + (long long)(b * SEQ) * QKVC + h * HD;
    const __half* Kg = Qg + DIMC;
    const __half* Vg = Qg + 2 * DIMC;

    #pragma unroll
    for (int t = 0; t < 2; t++) {
        int i = tid + t * 256;
        int r = i >> 3, c = i & 7;
        int gq = q0 + r;
        cpa16(shb + SM_Q + r * SROWB + c * 16, Qg + (long long)gq * QKVC + c * 8, gq < SEQ);
    }
    #pragma unroll
    for (int t = 0; t < 4; t++) {
        int i = tid + t * 256;
        int r = i >> 3, c = i & 7;
        cpa16(shb + SM_KV + r * SROWB + c * 16, Kg + (long long)r * QKVC + c * 8, r < SEQ);
    }
    cp_commit();

    uint32_t aq[4][4];

    for (int jb = 0; jb < 5; jb++) {
        if (jb < 4) {
            int s = (jb + 1) & 1;
            int kb0 = (jb + 1) * 128;
            #pragma unroll
            for (int t = 0; t < 4; t++) {
                int i = tid + t * 256;
                int r = i >> 3, c = i & 7;
                int gk = kb0 + r;
                cpa16(shb + SM_KV + s * KV_STG + r * SROWB + c * 16,
                      Kg + (long long)gk * QKVC + c * 8, gk < SEQ);
            }
            cp_commit();
            asm volatile("cp.async.wait_group 1;");
        } else {
            asm volatile("cp.async.wait_group 0;");
        }
        __syncthreads();
        if (jb == 0) {
            #pragma unroll
            for (int ks = 0; ks < 4; ks++)
                ldmA(aq[ks], shb + SM_Q, wm * 16, ks * 16, lane);
        }
        float acc[8][4];
        #pragma unroll
        for (int i = 0; i < 8; i++)
            #pragma unroll
            for (int r = 0; r < 4; r++) acc[i][r] = 0.f;

        uint32_t kbase = shb + SM_KV + (jb & 1) * KV_STG;
        #pragma unroll
        for (int ks = 0; ks < 4; ks++) {
            uint32_t bfr[8][2];
            #pragma unroll
            for (int nt = 0; nt < 8; nt += 2) {
                uint32_t bb[4];
                ldmB2(bb, kbase, wn * 64 + nt * 8, ks * 16, lane);
                bfr[nt][0] = bb[0]; bfr[nt][1] = bb[1];
                bfr[nt + 1][0] = bb[2]; bfr[nt + 1][1] = bb[3];
            }
            #pragma unroll
            for (int nt = 0; nt < 8; nt++) mma16(acc[nt], aq[ks], bfr[nt]);
        }
        #pragma unroll
        for (int nt = 0; nt < 8; nt++) {
            int col = jb * 128 + wn * 64 + nt * 8 + tg * 2;
            #pragma unroll
            for (int hf = 0; hf < 2; hf++) {
                int row = wm * 16 + group + hf * 8;
                float2 v = make_float2(acc[nt][hf * 2] * 0.125f, acc[nt][hf * 2 + 1] * 0.125f);
                *(float2*)(sh + SM_S + row * SRS + col * 4) = v;
            }
        }
        __syncthreads();
    }

    #pragma unroll
    for (int t = 0; t < 4; t++) {
        int i = tid + t * 256;
        int r = i >> 3, c = i & 7;
        cpa16(shb + SM_KV + r * SROWB + c * 16, Vg + (long long)r * QKVC + c * 8, r < SEQ);
    }
    cp_commit();

    #pragma unroll 1
    for (int rr = 0; rr < 8; rr++) {
        int row = warp * 8 + rr;
        const char* srow = sh + SM_S + row * SRS;
        float2 v[10];
        #pragma unroll
        for (int j = 0; j < 10; j++) {
            int c0 = j * 64 + lane * 2;
            float2 f = *(const float2*)(srow + c0 * 4);
            v[j].x = (c0     < SEQ) ? f.x : -1e30f;
            v[j].y = (c0 + 1 < SEQ) ? f.y : -1e30f;
        }
        bool in0 = lane < 10;

        float m0 = in0 ? fmaxf(v[0].x, v[0].y) : -1e30f;
        float m1 = in0 ? -1e30f : fmaxf(v[0].x, v[0].y);
        #pragma unroll
        for (int j = 1; j < 10; j++) m1 = fmaxf(m1, fmaxf(v[j].x, v[j].y));
        #pragma unroll
        for (int o = 16; o; o >>= 1) {
            m0 = fmaxf(m0, __shfl_xor_sync(0xffffffffu, m0, o));
            m1 = fmaxf(m1, __shfl_xor_sync(0xffffffffu, m1, o));
        }

        float s0 = 0.f, s1 = 0.f;
        {
            float mm = in0 ? m0 : m1;
            float ex = __expf(v[0].x - mm);
            float ey = __expf(v[0].y - mm);
            v[0].x = ex; v[0].y = ey;
            if (in0) s0 += ex + ey; else s1 += ex + ey;
        }
        #pragma unroll
        for (int j = 1; j < 10; j++) {
            int c0 = j * 64 + lane * 2;
            float ex = (c0     < SEQ) ? __expf(v[j].x - m1) : 0.f;
            float ey = (c0 + 1 < SEQ) ? __expf(v[j].y - m1) : 0.f;
            v[j].x = ex; v[j].y = ey;
            s1 += ex + ey;
        }
        #pragma unroll
        for (int o = 16; o; o >>= 1) {
            s0 += __shfl_xor_sync(0xffffffffu, s0, o);
            s1 += __shfl_xor_sync(0xffffffffu, s1, o);
        }
        float r0 = 1.0f / s0, r1 = 1.0f / s1;

        int gq = q0 + row;
        bool qok = gq < SEQ;
        float* wrow = out_w + ((long long)z * SEQ + gq) * SEQ;
        __half* hrow = (__half*)(sh + SM_S + row * SRS + 16 * (row & 7));
        {
            float rr0 = in0 ? r0 : r1;
            float2 o2 = make_float2(v[0].x * rr0, v[0].y * rr0);
            if (qok) __stcs((float2*)(wrow + lane * 2), o2);
            *(__half2*)(hrow + lane * 2) = __floats2half2_rn(o2.x, o2.y);
        }
        #pragma unroll
        for (int j = 1; j < 10; j++) {
            int c0 = j * 64 + lane * 2;
            float2 o2 = make_float2(v[j].x * r1, v[j].y * r1);
            if (c0 + 1 < SEQ) {
                if (qok) __stcs((float2*)(wrow + c0), o2);
                *(__half2*)(hrow + c0) = __floats2half2_rn(o2.x, o2.y);
            } else if (c0 < SEQ) {
                if (qok) __stcs(wrow + c0, o2.x);
                hrow[c0] = __float2half_rn(o2.x);
            }
        }
        if (lane < 22) *(__half2*)(hrow + SEQ + lane * 2) = __half2half2(__float2half(0.f));
    }
    __syncthreads();

    float oacc[4][4];
    #pragma unroll
    for (int i = 0; i < 4; i++)
        #pragma unroll
        for (int r = 0; r < 4; r++) oacc[i][r] = 0.f;

    for (int vb = 0; vb < 5; vb++) {
        if (vb < 4) {
            int s = (vb + 1) & 1;
            int v0 = (vb + 1) * 128;
            #pragma unroll
            for (int t = 0; t < 4; t++) {
                int i = tid + t * 256;
                int r = i >> 3, c = i & 7;
                int gk = v0 + r;
                cpa16(shb + SM_KV + s * KV_STG + r * SROWB + c * 16,
                      Vg + (long long)gk * QKVC + c * 8, gk < SEQ);
            }
            cp_commit();
            asm volatile("cp.async.wait_group 1;");
        } else {
            asm volatile("cp.async.wait_group 0;");
        }
        __syncthreads();
        uint32_t vbase = shb + SM_KV + (vb & 1) * KV_STG;
        #pragma unroll
        for (int ks = 0; ks < 8; ks++) {
            uint32_t a[4];
            {
                int row = wm * 16 + (lane & 15);
                int kcol = vb * 128 + ks * 16 + (lane >> 4) * 8;
                ldm4(a, shb + SM_S + row * SRS + 16 * (row & 7) + kcol * 2);
            }
            uint32_t bfr[4][2];
            #pragma unroll
            for (int nt = 0; nt < 4; nt += 2) {
                int krow = ks * 16 + (lane & 15);
                int ncol = wn * 32 + nt * 8 + ((lane >> 4) << 3);
                uint32_t bb[4];
                ldm4t(bb, vbase + krow * SROWB + ncol * 2);
                bfr[nt][0] = bb[0]; bfr[nt][1] = bb[1];
                bfr[nt + 1][0] = bb[2]; bfr[nt + 1][1] = bb[3];
            }
            #pragma unroll
            for (int nt = 0; nt < 4; nt++) mma16(oacc[nt], a, bfr[nt]);
        }
        __syncthreads();
    }

    #pragma unroll
    for (int nt = 0; nt < 4; nt++) {
        int col = wn * 32 + nt * 8 + tg * 2;
        #pragma unroll
        for (int hf = 0; hf < 2; hf++) {
            int row = wm * 16 + group + hf * 8;
            int gq = q0 + row;
            if (gq < SEQ) {
                __half2 hv = __floats2half2_rn(oacc[nt][hf * 2], oacc[nt][hf * 2 + 1]);
                *(__half2*)(och + (long long)(b * SEQ + gq) * DIMC + h * HD + col) = hv;
            }
        }
    }
}

// ---------------- fp16 GEMM (TN): BM = 32*MT tile (templated), 3-stage cp.async ----
#define BK 64
#define NSTG 3

template<int MT>
__global__ __launch_bounds__(256, 2)
void gemm_h(const __half* __restrict__ A, const __half* __restrict__ B,
            const float* __restrict__ bias, const float* __restrict__ res,
            float* __restrict__ Cf, __half* __restrict__ Ch,
            int M, int Nn, int K, int lda, int ldb, int ldc,
            float alpha, int act, int streamC) {
    constexpr int BM_ = 32 * MT;
    constexpr int TILE_A = BM_ * SROWB;
    constexpr int TILE_Bt = 128 * SROWB;
    constexpr int STG = TILE_A + TILE_Bt;
    extern __shared__ __align__(16) char sh[];
    uint32_t shb = (uint32_t)__cvta_generic_to_shared(sh);

    int tid = threadIdx.x, warp = tid >> 5, lane = tid & 31;
    int wm = warp >> 2, wn = warp & 3;
    int group = lane >> 2, tg = lane & 3;
    int row0 = blockIdx.y * BM_, col0 = blockIdx.x * 128;

    float acc[MT][4][4];
    #pragma unroll
    for (int i = 0; i < MT; i++)
        #pragma unroll
        for (int j = 0; j < 4; j++)
            #pragma unroll
            for (int r = 0; r < 4; r++) acc[i][j][r] = 0.f;

    auto load_tiles = [&](int s, int k0) {
        uint32_t a0 = shb + s * STG;
        uint32_t b0 = a0 + TILE_A;
        #pragma unroll
        for (int t = 0; t < BM_ / 32; t++) {
            int i = tid + t * 256;
            int r = i >> 3, c = i & 7;
            int gr = row0 + r;
            cpa16(a0 + r * SROWB + c * 16, A + (long long)gr * lda + k0 + c * 8, gr < M);
        }
        #pragma unroll
        for (int t = 0; t < 4; t++) {
            int i = tid + t * 256;
            int r = i >> 3, c = i & 7;
            int gn = col0 + r;
            cpa16(b0 + r * SROWB + c * 16, B + (long long)gn * ldb + k0 + c * 8, gn < Nn);
        }
    };

    auto compute = [&](int s) {
        uint32_t a0 = shb + s * STG;
        uint32_t b0 = a0 + TILE_A;
        #pragma unroll
        for (int ks = 0; ks < 4; ks++) {
            int kb = ks * 16;
            uint32_t a[MT][4], b[4][2];
            #pragma unroll
            for (int mt = 0; mt < MT; mt++)
                ldmA(a[mt], a0, wm * MT * 16 + mt * 16, kb, lane);
            #pragma unroll
            for (int nt = 0; nt < 4; nt += 2) {
                uint32_t bb[4];
                ldmB2(bb, b0, wn * 32 + nt * 8, kb, lane);
                b[nt][0] = bb[0]; b[nt][1] = bb[1];
                b[nt + 1][0] = bb[2]; b[nt + 1][1] = bb[3];
            }
            #pragma unroll
            for (int mt = 0; mt < MT; mt++)
                #pragma unroll
                for (int nt = 0; nt < 4; nt++)
                    mma16(acc[mt][nt], a[mt], b[nt]);
        }
    };

    int nT = K / BK;
    #pragma unroll
    for (int s = 0; s < NSTG - 1; s++) {
        if (s < nT) load_tiles(s, s * BK);
        cp_commit();
    }
    for (int t = 0; t < nT; t++) {
        asm volatile("cp.async.wait_group %0;" :: "n"(NSTG - 2));
        __syncthreads();
        int pf = t + NSTG - 1;
        if (pf < nT) load_tiles(pf % NSTG, pf * BK);
        cp_commit();
        compute(t % NSTG);
    }

    #pragma unroll
    for (int mt = 0; mt < MT; mt++) {
        #pragma unroll
        for (int nt = 0; nt < 4; nt++) {
            int gc = col0 + wn * 32 + nt * 8 + tg * 2;
            if (gc >= Nn) continue;
            float bx = 0.f, by = 0.f;
            if (bias) { bx = bias[gc]; by = bias[gc + 1]; }
            #pragma unroll
            for (int hf = 0; hf < 2; hf++) {
                int gm = row0 + wm * MT * 16 + mt * 16 + group + hf * 8;
                if (gm >= M) continue;
                float v0 = acc[mt][nt][hf * 2]     * alpha + bx;
                float v1 = acc[mt][nt][hf * 2 + 1] * alpha + by;
                if (act == 1) {
                    v0 = gelu_exact(v0);
                    v1 = gelu_exact(v1);
                }
                if (res) {
                    float2 rr = *(const float2*)(res + (long long)gm * ldc + gc);
                    v0 += rr.x; v1 += rr.y;
                }
                if (Cf) {
                    if (streamC)
                        __stcs((float2*)(Cf + (long long)gm * ldc + gc), make_float2(v0, v1));
                    else
                        *(float2*)(Cf + (long long)gm * ldc + gc) = make_float2(v0, v1);
                }
                if (Ch) *(__half2*)(Ch + (long long)gm * ldc + gc) =
                            __floats2half2_rn(v0, v1);
            }
        }
    }
}

#define GEMM_SMEM4 (NSTG * (128 + 128) * SROWB)   // 110592
#define GEMM_SMEM3 (NSTG * (96 + 128) * SROWB)    //  96768

// ---------------- host-side orchestration -------------------------------------------
extern "C" void kernel_launch(void* const* d_in, const int* in_sizes, int n_in,
                              void* d_out, int out_size) {
    const float* x      = (const float*)d_in[0];
    const float* qkv_w  = (const float*)d_in[1];
    const float* qkv_b  = (const float*)d_in[2];
    const float* proj_w = (const float*)d_in[3];
    const float* proj_b = (const float*)d_in[4];
    const float* ln1_g  = (const float*)d_in[5];
    const float* ln1_b  = (const float*)d_in[6];
    const float* ln2_g  = (const float*)d_in[7];
    const float* ln2_b  = (const float*)d_in[8];
    const float* fc1_w  = (const float*)d_in[9];
    const float* fc1_b  = (const float*)d_in[10];
    const float* fc2_w  = (const float*)d_in[11];
    const float* fc2_b  = (const float*)d_in[12];

    float* out_x = (float*)d_out;
    float* out_w = out_x + (long long)ROWS * DIMC;

    __half *h1h, *qkvh, *och, *mlph, *qkvwh, *projwh, *fc1wh, *fc2wh;
    float* x2;
    cudaGetSymbolAddress((void**)&h1h,   g_h1h);
    cudaGetSymbolAddress((void**)&qkvh,  g_qkvh);
    cudaGetSymbolAddress((void**)&och,   g_och);
    cudaGetSymbolAddress((void**)&mlph,  g_mlph);
    cudaGetSymbolAddress((void**)&x2,    g_x2);
    cudaGetSymbolAddress((void**)&qkvwh, g_qkvwh);
    cudaGetSymbolAddress((void**)&projwh,g_projwh);
    cudaGetSymbolAddress((void**)&fc1wh, g_fc1wh);
    cudaGetSymbolAddress((void**)&fc2wh, g_fc2wh);

    cudaFuncSetAttribute((const void*)gemm_h<4>,
                         cudaFuncAttributeMaxDynamicSharedMemorySize, GEMM_SMEM4);
    cudaFuncSetAttribute((const void*)gemm_h<3>,
                         cudaFuncAttributeMaxDynamicSharedMemorySize, GEMM_SMEM3);
    cudaFuncSetAttribute((const void*)attn_fused,
                         cudaFuncAttributeMaxDynamicSharedMemorySize, ATTN_SMEM);

    static cudaStream_t sA = nullptr, sB = nullptr, sW = nullptr;
    static cudaEvent_t e0 = nullptr, eW = nullptr, eA = nullptr, eB = nullptr;
    if (!sA) {
        cudaStreamCreateWithFlags(&sA, cudaStreamNonBlocking);
        cudaStreamCreateWithFlags(&sB, cudaStreamNonBlocking);
        cudaStreamCreateWithFlags(&sW, cudaStreamNonBlocking);
        cudaEventCreateWithFlags(&e0, cudaEventDisableTiming);
        cudaEventCreateWithFlags(&eW, cudaEventDisableTiming);
        cudaEventCreateWithFlags(&eA, cudaEventDisableTiming);
        cudaEventCreateWithFlags(&eB, cudaEventDisableTiming);
    }

    cudaEventRecord(e0, 0);
    cudaStreamWaitEvent(sW, e0, 0);
    cudaStreamWaitEvent(sA, e0, 0);
    cudaStreamWaitEvent(sB, e0, 0);

    f2h4<<<(QKVC * DIMC / 4 + 255) / 256, 256, 0, sW>>>((const float4*)qkv_w, (__half2*)qkvwh, QKVC * DIMC / 4);
    f2h4<<<(DIMC * DIMC / 4 + 255) / 256, 256, 0, sW>>>((const float4*)proj_w, (__half2*)projwh, DIMC * DIMC / 4);
    f2h4<<<(HIDDEN * DIMC / 4 + 255) / 256, 256, 0, sW>>>((const float4*)fc1_w, (__half2*)fc1wh, HIDDEN * DIMC / 4);
    f2h4<<<(DIMC * HIDDEN / 4 + 255) / 256, 256, 0, sW>>>((const float4*)fc2_w, (__half2*)fc2wh, DIMC * HIDDEN / 4);
    cudaEventRecord(eW, sW);

    const int MB128 = (HROWS + 127) / 128;   // 38
    const int MB96  = (HROWS + 95) / 96;     // 50

    for (int hf = 0; hf < 2; hf++) {
        cudaStream_t s = hf ? sB : sA;
        long long r0 = (long long)hf * HROWS;
        const float* xh   = x   + r0 * DIMC;
        __half* h1h_h     = h1h + r0 * DIMC;
        __half* qkvh_h    = qkvh + r0 * QKVC;
        __half* och_h     = och + r0 * DIMC;
        __half* mlph_h    = mlph + r0 * HIDDEN;
        float*  x2_h      = x2  + r0 * DIMC;
        float*  outx_h    = out_x + r0 * DIMC;
        float*  outw_h    = out_w + (long long)hf * HBATCH * NHEADS * SEQ * SEQ;

        ln_kernel<<<HROWS, 192, 0, s>>>(xh, ln1_g, ln1_b, h1h_h);
        cudaStreamWaitEvent(s, eW, 0);

        gemm_h<4><<<dim3(QKVC / 128, MB128, 1), 256, GEMM_SMEM4, s>>>(
            h1h_h, qkvwh, qkv_b, nullptr, nullptr, qkvh_h,
            HROWS, QKVC, DIMC, DIMC, DIMC, QKVC, 1.0f, 0, 0);

        attn_fused<<<dim3((SEQ + QS - 1) / QS, HBATCH * NHEADS), 256, ATTN_SMEM, s>>>(
            qkvh_h, outw_h, och_h);

        gemm_h<3><<<dim3(DIMC / 128, MB96, 1), 256, GEMM_SMEM3, s>>>(
            och_h, projwh, proj_b, xh, x2_h, nullptr,
            HROWS, DIMC, DIMC, DIMC, DIMC, DIMC, 1.0f, 0, 0);

        ln_kernel<<<HROWS, 192, 0, s>>>(x2_h, ln2_g, ln2_b, h1h_h);

        gemm_h<4><<<dim3(HIDDEN / 128, MB128, 1), 256, GEMM_SMEM4, s>>>(
            h1h_h, fc1wh, fc1_b, nullptr, nullptr, mlph_h,
            HROWS, HIDDEN, DIMC, DIMC, DIMC, HIDDEN, 1.0f, 1, 0);

        // final output: streaming stores (never re-read)
        gemm_h<3><<<dim3(DIMC / 128, MB96, 1), 256, GEMM_SMEM3, s>>>(
            mlph_h, fc2wh, fc2_b, x2_h, outx_h, nullptr,
            HROWS, DIMC, HIDDEN, HIDDEN, HIDDEN, DIMC, 1.0f, 0, 1);
    }

    cudaEventRecord(eA, sA);
    cudaEventRecord(eB, sB);
    cudaStreamWaitEvent(0, eA, 0);
    cudaStreamWaitEvent(0, eB, 0);
}

// round 15
// speedup vs baseline: 1.1370x; 1.1370x over previous
#include <cuda_runtime.h>
#include <cuda_fp16.h>
#include <math.h>
#include <stdint.h>

// Problem constants
#define DIMC   768
#define NHEADS 12
#define HD     64
#define BATCH  16
#define SEQ    596
#define ROWS   (BATCH*SEQ)      // 9536
#define HBATCH (BATCH/2)
#define HROWS  (HBATCH*SEQ)     // 4768
#define QKVC   2304
#define HIDDEN 3072
#define CLSK   20

// ---------------- scratch ---------------------------------------------------------
__device__ __half g_h1h [ROWS*DIMC];
__device__ __half g_qkvh[ROWS*QKVC];
__device__ __half g_och [ROWS*DIMC];
__device__ __half g_mlph[ROWS*HIDDEN];
__device__ float  g_x2  [ROWS*DIMC];
__device__ __half g_qkvwh[QKVC*DIMC];
__device__ __half g_projwh[DIMC*DIMC];
__device__ __half g_fc1wh[HIDDEN*DIMC];
__device__ __half g_fc2wh[DIMC*HIDDEN];

// ---------------- fp32 -> fp16, vectorized ----------------------------------------
__global__ void f2h4(const float4* __restrict__ a, __half2* __restrict__ o, int n4) {
    int i = blockIdx.x * 256 + threadIdx.x;
    if (i < n4) {
        float4 v = a[i];
        o[2 * i]     = __floats2half2_rn(v.x, v.y);
        o[2 * i + 1] = __floats2half2_rn(v.z, v.w);
    }
}

// ---------------- LayerNorm: 192 thr/row, single pass, register-cached -------------
__global__ __launch_bounds__(192)
void ln_kernel(const float* __restrict__ x,
               const float* __restrict__ g,
               const float* __restrict__ b,
               __half* __restrict__ out) {
    int row = blockIdx.x;
    int t = threadIdx.x;
    const float4* xr = (const float4*)(x + (long long)row * DIMC);
    float4 v = xr[t];

    float s  = v.x + v.y + v.z + v.w;
    float s2 = v.x * v.x + v.y * v.y + v.z * v.z + v.w * v.w;
    #pragma unroll
    for (int o = 16; o; o >>= 1) {
        s  += __shfl_xor_sync(0xffffffffu, s,  o);
        s2 += __shfl_xor_sync(0xffffffffu, s2, o);
    }
    __shared__ float rs[6], rs2[6];
    int wid = t >> 5, lid = t & 31;
    if (lid == 0) { rs[wid] = s; rs2[wid] = s2; }
    __syncthreads();
    if (t < 32) {
        float a  = (t < 6) ? rs[t]  : 0.f;
        float a2 = (t < 6) ? rs2[t] : 0.f;
        #pragma unroll
        for (int o = 4; o; o >>= 1) {
            a  += __shfl_xor_sync(0xffffffffu, a,  o);
            a2 += __shfl_xor_sync(0xffffffffu, a2, o);
        }
        if (t == 0) { rs[0] = a; rs2[0] = a2; }
    }
    __syncthreads();
    float mean = rs[0] * (1.0f / DIMC);
    float var  = rs2[0] * (1.0f / DIMC) - mean * mean;
    float inv  = rsqrtf(var + 1e-5f);

    float4 gg = *(const float4*)(g + t * 4);
    float4 bb = *(const float4*)(b + t * 4);
    float o0 = (v.x - mean) * inv * gg.x + bb.x;
    float o1 = (v.y - mean) * inv * gg.y + bb.y;
    float o2 = (v.z - mean) * inv * gg.z + bb.z;
    float o3 = (v.w - mean) * inv * gg.w + bb.w;
    __half2 h01 = __floats2half2_rn(o0, o1);
    __half2 h23 = __floats2half2_rn(o2, o3);
    uint2 pk = make_uint2(*(uint32_t*)&h01, *(uint32_t*)&h23);
    *(uint2*)(out + (long long)row * DIMC + t * 4) = pk;
}

// ---------------- shared helpers ---------------------------------------------------
#define SROWB 144

__device__ __forceinline__ void mma16(float* c, const uint32_t* a, const uint32_t* b) {
    asm volatile(
        "mma.sync.aligned.m16n8k16.row.col.f32.f16.f16.f32 "
        "{%0,%1,%2,%3}, {%4,%5,%6,%7}, {%8,%9}, {%0,%1,%2,%3};"
        : "+f"(c[0]), "+f"(c[1]), "+f"(c[2]), "+f"(c[3])
        : "r"(a[0]), "r"(a[1]), "r"(a[2]), "r"(a[3]), "r"(b[0]), "r"(b[1]));
}
__device__ __forceinline__ void cpa16(uint32_t dst, const void* src, bool pred) {
    unsigned ssz = pred ? 16u : 0u;
    asm volatile("cp.async.cg.shared.global [%0], [%1], 16, %2;"
                 :: "r"(dst), "l"(src), "r"(ssz));
}
__device__ __forceinline__ void cp_commit() { asm volatile("cp.async.commit_group;"); }

__device__ __forceinline__ void ldmA(uint32_t* a, uint32_t base, int m0, int kb, int lane) {
    uint32_t addr = base + (uint32_t)(m0 + (lane & 15)) * SROWB
                  + (uint32_t)(kb + (lane >> 4) * 8) * 2;
    asm volatile("ldmatrix.sync.aligned.m8n8.x4.shared.b16 {%0,%1,%2,%3}, [%4];"
                 : "=r"(a[0]), "=r"(a[1]), "=r"(a[2]), "=r"(a[3]) : "r"(addr));
}
__device__ __forceinline__ void ldmB2(uint32_t* b, uint32_t base, int n0, int kb, int lane) {
    uint32_t addr = base + (uint32_t)(n0 + (lane & 7) + ((lane >> 4) * 8)) * SROWB
                  + (uint32_t)(kb + ((lane >> 3) & 1) * 8) * 2;
    asm volatile("ldmatrix.sync.aligned.m8n8.x4.shared.b16 {%0,%1,%2,%3}, [%4];"
                 : "=r"(b[0]), "=r"(b[1]), "=r"(b[2]), "=r"(b[3]) : "r"(addr));
}
__device__ __forceinline__ void ldm4(uint32_t* r, uint32_t addr) {
    asm volatile("ldmatrix.sync.aligned.m8n8.x4.shared.b16 {%0,%1,%2,%3}, [%4];"
                 : "=r"(r[0]), "=r"(r[1]), "=r"(r[2]), "=r"(r[3]) : "r"(addr));
}
__device__ __forceinline__ void ldm4t(uint32_t* r, uint32_t addr) {
    asm volatile("ldmatrix.sync.aligned.m8n8.x4.trans.shared.b16 {%0,%1,%2,%3}, [%4];"
                 : "=r"(r[0]), "=r"(r[1]), "=r"(r[2]), "=r"(r[3]) : "r"(addr));
}

// ---------------- fused attention: QK^T -> split softmax -> AV ---------------------
#define QS 64
#define SRS 2560
#define KV_STG (128*SROWB)
#define SM_Q  0
#define SM_KV 9216
#define SM_S  46080
#define ATTN_SMEM (SM_S + QS*SRS)     // 209920

__global__ __launch_bounds__(256, 1)
void attn_fused(const __half* __restrict__ qkvh,
                float* __restrict__ out_w,
                __half* __restrict__ och) {
    extern __shared__ __align__(16) char sh[];
    uint32_t shb = (uint32_t)__cvta_generic_to_shared(sh);

    int z = blockIdx.y;
    int b = z / NHEADS, h = z % NHEADS;
    int q0 = blockIdx.x * QS;
    int tid = threadIdx.x, warp = tid >> 5, lane = tid & 31;
    int wm = warp >> 1, wn = warp & 1;
    int group = lane >> 2, tg = lane & 3;

    const __half* Qg = qkvh + (long long)(b * SEQ) * QKVC + h * HD;
    const __half* Kg = Qg + DIMC;
    const __half* Vg = Qg + 2 * DIMC;

    #pragma unroll
    for (int t = 0; t < 2; t++) {
        int i = tid + t * 256;
        int r = i >> 3, c = i & 7;
        int gq = q0 + r;
        cpa16(shb + SM_Q + r * SROWB + c * 16, Qg + (long long)gq * QKVC + c * 8, gq < SEQ);
    }
    #pragma unroll
    for (int t = 0; t < 4; t++) {
        int i = tid + t * 256;
        int r = i >> 3, c = i & 7;
        cpa16(shb + SM_KV + r * SROWB + c * 16, Kg + (long long)r * QKVC + c * 8, r < SEQ);
    }
    cp_commit();

    uint32_t aq[4][4];

    for (int jb = 0; jb < 5; jb++) {
        if (jb < 4) {
            int s = (jb + 1) & 1;
            int kb0 = (jb + 1) * 128;
            #pragma unroll
            for (int t = 0; t < 4; t++) {
                int i = tid + t * 256;
                int r = i >> 3, c = i & 7;
                int gk = kb0 + r;
                cpa16(shb + SM_KV + s * KV_STG + r * SROWB + c * 16,
                      Kg + (long long)gk * QKVC + c * 8, gk < SEQ);
            }
            cp_commit();
            asm volatile("cp.async.wait_group 1;");
        } else {
            asm volatile("cp.async.wait_group 0;");
        }
        __syncthreads();
        if (jb == 0) {
            #pragma unroll
            for (int ks = 0; ks < 4; ks++)
                ldmA(aq[ks], shb + SM_Q, wm * 16, ks * 16, lane);
        }
        float acc[8][4];
        #pragma unroll
        for (int i = 0; i < 8; i++)
            #pragma unroll
            for (int r = 0; r < 4; r++) acc[i][r] = 0.f;

        uint32_t kbase = shb + SM_KV + (jb & 1) * KV_STG;
        #pragma unroll
        for (int ks = 0; ks < 4; ks++) {
            uint32_t bfr[8][2];
            #pragma unroll
            for (int nt = 0; nt < 8; nt += 2) {
                uint32_t bb[4];
                ldmB2(bb, kbase, wn * 64 + nt * 8, ks * 16, lane);
                bfr[nt][0] = bb[0]; bfr[nt][1] = bb[1];
                bfr[nt + 1][0] = bb[2]; bfr[nt + 1][1] = bb[3];
            }
            #pragma unroll
            for (int nt = 0; nt < 8; nt++) mma16(acc[nt], aq[ks], bfr[nt]);
        }
        #pragma unroll
        for (int nt = 0; nt < 8; nt++) {
            int col = jb * 128 + wn * 64 + nt * 8 + tg * 2;
            #pragma unroll
            for (int hf = 0; hf < 2; hf++) {
                int row = wm * 16 + group + hf * 8;
                float2 v = make_float2(acc[nt][hf * 2] * 0.125f, acc[nt][hf * 2 + 1] * 0.125f);
                *(float2*)(sh + SM_S + row * SRS + col * 4) = v;
            }
        }
        __syncthreads();
    }

    #pragma unroll
    for (int t = 0; t < 4; t++) {
        int i = tid + t * 256;
        int r = i >> 3, c = i & 7;
        cpa16(shb + SM_KV + r * SROWB + c * 16, Vg + (long long)r * QKVC + c * 8, r < SEQ);
    }
    cp_commit();

    #pragma unroll 1
    for (int rr = 0; rr < 8; rr++) {
        int row = warp * 8 + rr;
        const char* srow = sh + SM_S + row * SRS;
        float2 v[10];
        #pragma unroll
        for (int j = 0; j < 10; j++) {
            int c0 = j * 64 + lane * 2;
            float2 f = *(const float2*)(srow + c0 * 4);
            v[j].x = (c0     < SEQ) ? f.x : -1e30f;
            v[j].y = (c0 + 1 < SEQ) ? f.y : -1e30f;
        }
        bool in0 = lane < 10;

        float m0 = in0 ? fmaxf(v[0].x, v[0].y) : -1e30f;
        float m1 = in0 ? -1e30f : fmaxf(v[0].x, v[0].y);
        #pragma unroll
        for (int j = 1; j < 10; j++) m1 = fmaxf(m1, fmaxf(v[j].x, v[j].y));
        #pragma unroll
        for (int o = 16; o; o >>= 1) {
            m0 = fmaxf(m0, __shfl_xor_sync(0xffffffffu, m0, o));
            m1 = fmaxf(m1, __shfl_xor_sync(0xffffffffu, m1, o));
        }

        float s0 = 0.f, s1 = 0.f;
        {
            float mm = in0 ? m0 : m1;
            float ex = __expf(v[0].x - mm);
            float ey = __expf(v[0].y - mm);
            v[0].x = ex; v[0].y = ey;
            if (in0) s0 += ex + ey; else s1 += ex + ey;
        }
        #pragma unroll
        for (int j = 1; j < 10; j++) {
            int c0 = j * 64 + lane * 2;
            float ex = (c0     < SEQ) ? __expf(v[j].x - m1) : 0.f;
            float ey = (c0 + 1 < SEQ) ? __expf(v[j].y - m1) : 0.f;
            v[j].x = ex; v[j].y = ey;
            s1 += ex + ey;
        }
        #pragma unroll
        for (int o = 16; o; o >>= 1) {
            s0 += __shfl_xor_sync(0xffffffffu, s0, o);
            s1 += __shfl_xor_sync(0xffffffffu, s1, o);
        }
        float r0 = 1.0f / s0, r1 = 1.0f / s1;

        int gq = q0 + row;
        bool qok = gq < SEQ;
        float* wrow = out_w + ((long long)z * SEQ + gq) * SEQ;
        __half* hrow = (__half*)(sh + SM_S + row * SRS + 16 * (row & 7));
        {
            float rr0 = in0 ? r0 : r1;
            float2 o2 = make_float2(v[0].x * rr0, v[0].y * rr0);
            if (qok) __stcs((float2*)(wrow + lane * 2), o2);
            *(__half2*)(hrow + lane * 2) = __floats2half2_rn(o2.x, o2.y);
        }
        #pragma unroll
        for (int j = 1; j < 10; j++) {
            int c0 = j * 64 + lane * 2;
            float2 o2 = make_float2(v[j].x * r1, v[j].y * r1);
            if (c0 + 1 < SEQ) {
                if (qok) __stcs((float2*)(wrow + c0), o2);
                *(__half2*)(hrow + c0) = __floats2half2_rn(o2.x, o2.y);
            } else if (c0 < SEQ) {
                if (qok) __stcs(wrow + c0, o2.x);
                hrow[c0] = __float2half_rn(o2.x);
            }
        }
        if (lane < 22) *(__half2*)(hrow + SEQ + lane * 2) = __half2half2(__float2half(0.f));
    }
    __syncthreads();

    float oacc[4][4];
    #pragma unroll
    for (int i = 0; i < 4; i++)
        #pragma unroll
        for (int r = 0; r < 4; r++) oacc[i][r] = 0.f;

    for (int vb = 0; vb < 5; vb++) {
        if (vb < 4) {
            int s = (vb + 1) & 1;
            int v0 = (vb + 1) * 128;
            #pragma unroll
            for (int t = 0; t < 4; t++) {
                int i = tid + t * 256;
                int r = i >> 3, c = i & 7;
                int gk = v0 + r;
                cpa16(shb + SM_KV + s * KV_STG + r * SROWB + c * 16,
                      Vg + (long long)gk * QKVC + c * 8, gk < SEQ);
            }
            cp_commit();
            asm volatile("cp.async.wait_group 1;");
        } else {
            asm volatile("cp.async.wait_group 0;");
        }
        __syncthreads();
        uint32_t vbase = shb + SM_KV + (vb & 1) * KV_STG;
        #pragma unroll
        for (int ks = 0; ks < 8; ks++) {
            uint32_t a[4];
            {
                int row = wm * 16 + (lane & 15);
                int kcol = vb * 128 + ks * 16 + (lane >> 4) * 8;
                ldm4(a, shb + SM_S + row * SRS + 16 * (row & 7) + kcol * 2);
            }
            uint32_t bfr[4][2];
            #pragma unroll
            for (int nt = 0; nt < 4; nt += 2) {
                int krow = ks * 16 + (lane & 15);
                int ncol = wn * 32 + nt * 8 + ((lane >> 4) << 3);
                uint32_t bb[4];
                ldm4t(bb, vbase + krow * SROWB + ncol * 2);
                bfr[nt][0] = bb[0]; bfr[nt][1] = bb[1];
                bfr[nt + 1][0] = bb[2]; bfr[nt + 1][1] = bb[3];
            }
            #pragma unroll
            for (int nt = 0; nt < 4; nt++) mma16(oacc[nt], a, bfr[nt]);
        }
        __syncthreads();
    }

    #pragma unroll
    for (int nt = 0; nt < 4; nt++) {
        int col = wn * 32 + nt * 8 + tg * 2;
        #pragma unroll
        for (int hf = 0; hf < 2; hf++) {
            int row = wm * 16 + group + hf * 8;
            int gq = q0 + row;
            if (gq < SEQ) {
                __half2 hv = __floats2half2_rn(oacc[nt][hf * 2], oacc[nt][hf * 2 + 1]);
                *(__half2*)(och + (long long)(b * SEQ + gq) * DIMC + h * HD + col) = hv;
            }
        }
    }
}

// ---------------- fp16 GEMM (TN): 128x128 tile, 256 thr, 2 CTA/SM, 3 stages --------
#define BK 64
#define NSTG 3
#define TILE_A (128*SROWB)
#define TILE_Bt (128*SROWB)
#define STG (TILE_A + TILE_Bt)
#define GEMM_SMEM (NSTG*STG)        // 110592

__global__ __launch_bounds__(256, 2)
void gemm_h(const __half* __restrict__ A, const __half* __restrict__ B,
            const float* __restrict__ bias, const float* __restrict__ res,
            float* __restrict__ Cf, __half* __restrict__ Ch,
            int M, int Nn, int K, int lda, int ldb, int ldc,
            float alpha, int act) {
    extern __shared__ __align__(16) char sh[];
    uint32_t shb = (uint32_t)__cvta_generic_to_shared(sh);

    int tid = threadIdx.x, warp = tid >> 5, lane = tid & 31;
    int wm = warp >> 2, wn = warp & 3;
    int group = lane >> 2, tg = lane & 3;
    int row0 = blockIdx.y * 128, col0 = blockIdx.x * 128;

    float acc[4][4][4];
    #pragma unroll
    for (int i = 0; i < 4; i++)
        #pragma unroll
        for (int j = 0; j < 4; j++)
            #pragma unroll
            for (int r = 0; r < 4; r++) acc[i][j][r] = 0.f;

    auto load_tiles = [&](int s, int k0) {
        uint32_t a0 = shb + s * STG;
        uint32_t b0 = a0 + TILE_A;
        #pragma unroll
        for (int t = 0; t < 4; t++) {
            int i = tid + t * 256;
            int r = i >> 3, c = i & 7;
            int gr = row0 + r;
            cpa16(a0 + r * SROWB + c * 16, A + (long long)gr * lda + k0 + c * 8, gr < M);
        }
        #pragma unroll
        for (int t = 0; t < 4; t++) {
            int i = tid + t * 256;
            int r = i >> 3, c = i & 7;
            int gn = col0 + r;
            cpa16(b0 + r * SROWB + c * 16, B + (long long)gn * ldb + k0 + c * 8, gn < Nn);
        }
    };

    auto compute = [&](int s) {
        uint32_t a0 = shb + s * STG;
        uint32_t b0 = a0 + TILE_A;
        #pragma unroll
        for (int ks = 0; ks < 4; ks++) {
            int kb = ks * 16;
            uint32_t a[4][4], b[4][2];
            #pragma unroll
            for (int mt = 0; mt < 4; mt++)
                ldmA(a[mt], a0, wm * 64 + mt * 16, kb, lane);
            #pragma unroll
            for (int nt = 0; nt < 4; nt += 2) {
                uint32_t bb[4];
                ldmB2(bb, b0, wn * 32 + nt * 8, kb, lane);
                b[nt][0] = bb[0]; b[nt][1] = bb[1];
                b[nt + 1][0] = bb[2]; b[nt + 1][1] = bb[3];
            }
            #pragma unroll
            for (int mt = 0; mt < 4; mt++)
                #pragma unroll
                for (int nt = 0; nt < 4; nt++)
                    mma16(acc[mt][nt], a[mt], b[nt]);
        }
    };

    int nT = K / BK;
    #pragma unroll
    for (int s = 0; s < NSTG - 1; s++) {
        if (s < nT) load_tiles(s, s * BK);
        cp_commit();
    }
    for (int t = 0; t < nT; t++) {
        asm volatile("cp.async.wait_group %0;" :: "n"(NSTG - 2));
        __syncthreads();
        int pf = t + NSTG - 1;
        if (pf < nT) load_tiles(pf % NSTG, pf * BK);
        cp_commit();
        compute(t % NSTG);
    }

    #pragma unroll
    for (int mt = 0; mt < 4; mt++) {
        #pragma unroll
        for (int nt = 0; nt < 4; nt++) {
            int gc = col0 + wn * 32 + nt * 8 + tg * 2;
            if (gc >= Nn) continue;
            float bx = 0.f, by = 0.f;
            if (bias) { bx = bias[gc]; by = bias[gc + 1]; }
            #pragma unroll
            for (int hf = 0; hf < 2; hf++) {
                int gm = row0 + wm * 64 + mt * 16 + group + hf * 8;
                if (gm >= M) continue;
                float v0 = acc[mt][nt][hf * 2]     * alpha + bx;
                float v1 = acc[mt][nt][hf * 2 + 1] * alpha + by;
                if (act == 1) {
                    v0 = 0.5f * v0 * (1.0f + erff(v0 * 0.70710678118654752f));
                    v1 = 0.5f * v1 * (1.0f + erff(v1 * 0.70710678118654752f));
                }
                if (res) {
                    float2 rr = *(const float2*)(res + (long long)gm * ldc + gc);
                    v0 += rr.x; v1 += rr.y;
                }
                if (Cf) *(float2*)(Cf + (long long)gm * ldc + gc) = make_float2(v0, v1);
                if (Ch) *(__half2*)(Ch + (long long)gm * ldc + gc) =
                            __floats2half2_rn(v0, v1);
            }
        }
    }
}

// ---------------- host-side orchestration -------------------------------------------
extern "C" void kernel_launch(void* const* d_in, const int* in_sizes, int n_in,
                              void* d_out, int out_size) {
    const float* x      = (const float*)d_in[0];
    const float* qkv_w  = (const float*)d_in[1];
    const float* qkv_b  = (const float*)d_in[2];
    const float* proj_w = (const float*)d_in[3];
    const float* proj_b = (const float*)d_in[4];
    const float* ln1_g  = (const float*)d_in[5];
    const float* ln1_b  = (const float*)d_in[6];
    const float* ln2_g  = (const float*)d_in[7];
    const float* ln2_b  = (const float*)d_in[8];
    const float* fc1_w  = (const float*)d_in[9];
    const float* fc1_b  = (const float*)d_in[10];
    const float* fc2_w  = (const float*)d_in[11];
    const float* fc2_b  = (const float*)d_in[12];

    float* out_x = (float*)d_out;
    float* out_w = out_x + (long long)ROWS * DIMC;

    __half *h1h, *qkvh, *och, *mlph, *qkvwh, *projwh, *fc1wh, *fc2wh;
    float* x2;
    cudaGetSymbolAddress((void**)&h1h,   g_h1h);
    cudaGetSymbolAddress((void**)&qkvh,  g_qkvh);
    cudaGetSymbolAddress((void**)&och,   g_och);
    cudaGetSymbolAddress((void**)&mlph,  g_mlph);
    cudaGetSymbolAddress((void**)&x2,    g_x2);
    cudaGetSymbolAddress((void**)&qkvwh, g_qkvwh);
    cudaGetSymbolAddress((void**)&projwh,g_projwh);
    cudaGetSymbolAddress((void**)&fc1wh, g_fc1wh);
    cudaGetSymbolAddress((void**)&fc2wh, g_fc2wh);

    cudaFuncSetAttribute((const void*)gemm_h,
                         cudaFuncAttributeMaxDynamicSharedMemorySize, GEMM_SMEM);
    cudaFuncSetAttribute((const void*)attn_fused,
                         cudaFuncAttributeMaxDynamicSharedMemorySize, ATTN_SMEM);

    static cudaStream_t sA = nullptr, sB = nullptr, sW = nullptr;
    static cudaEvent_t e0 = nullptr, eW = nullptr, eA = nullptr, eB = nullptr;
    if (!sA) {
        cudaStreamCreateWithFlags(&sA, cudaStreamNonBlocking);
        cudaStreamCreateWithFlags(&sB, cudaStreamNonBlocking);
        cudaStreamCreateWithFlags(&sW, cudaStreamNonBlocking);
        cudaEventCreateWithFlags(&e0, cudaEventDisableTiming);
        cudaEventCreateWithFlags(&eW, cudaEventDisableTiming);
        cudaEventCreateWithFlags(&eA, cudaEventDisableTiming);
        cudaEventCreateWithFlags(&eB, cudaEventDisableTiming);
    }

    cudaEventRecord(e0, 0);
    cudaStreamWaitEvent(sW, e0, 0);
    cudaStreamWaitEvent(sA, e0, 0);
    cudaStreamWaitEvent(sB, e0, 0);

    f2h4<<<(QKVC * DIMC / 4 + 255) / 256, 256, 0, sW>>>((const float4*)qkv_w, (__half2*)qkvwh, QKVC * DIMC / 4);
    f2h4<<<(DIMC * DIMC / 4 + 255) / 256, 256, 0, sW>>>((const float4*)proj_w, (__half2*)projwh, DIMC * DIMC / 4);
    f2h4<<<(HIDDEN * DIMC / 4 + 255) / 256, 256, 0, sW>>>((const float4*)fc1_w, (__half2*)fc1wh, HIDDEN * DIMC / 4);
    f2h4<<<(DIMC * HIDDEN / 4 + 255) / 256, 256, 0, sW>>>((const float4*)fc2_w, (__half2*)fc2wh, DIMC * HIDDEN / 4);
    cudaEventRecord(eW, sW);

    const int MBh = (HROWS + 127) / 128;   // 38

    for (int hf = 0; hf < 2; hf++) {
        cudaStream_t s = hf ? sB : sA;
        long long r0 = (long long)hf * HROWS;
        const float* xh   = x   + r0 * DIMC;
        __half* h1h_h     = h1h + r0 * DIMC;
        __half* qkvh_h    = qkvh + r0 * QKVC;
        __half* och_h     = och + r0 * DIMC;
        __half* mlph_h    = mlph + r0 * HIDDEN;
        float*  x2_h      = x2  + r0 * DIMC;
        float*  outx_h    = out_x + r0 * DIMC;
        float*  outw_h    = out_w + (long long)hf * HBATCH * NHEADS * SEQ * SEQ;

        ln_kernel<<<HROWS, 192, 0, s>>>(xh, ln1_g, ln1_b, h1h_h);
        cudaStreamWaitEvent(s, eW, 0);

        gemm_h<<<dim3(QKVC / 128, MBh, 1), 256, GEMM_SMEM, s>>>(
            h1h_h, qkvwh, qkv_b, nullptr, nullptr, qkvh_h,
            HROWS, QKVC, DIMC, DIMC, DIMC, QKVC, 1.0f, 0);

        attn_fused<<<dim3((SEQ + QS - 1) / QS, HBATCH * NHEADS), 256, ATTN_SMEM, s>>>(
            qkvh_h, outw_h, och_h);

        gemm_h<<<dim3(DIMC / 128, MBh, 1), 256, GEMM_SMEM, s>>>(
            och_h, projwh, proj_b, xh, x2_h, nullptr,
            HROWS, DIMC, DIMC, DIMC, DIMC, DIMC, 1.0f, 0);

        ln_kernel<<<HROWS, 192, 0, s>>>(x2_h, ln2_g, ln2_b, h1h_h);

        gemm_h<<<dim3(HIDDEN / 128, MBh, 1), 256, GEMM_SMEM, s>>>(
            h1h_h, fc1wh, fc1_b, nullptr, nullptr, mlph_h,
            HROWS, HIDDEN, DIMC, DIMC, DIMC, HIDDEN, 1.0f, 1);

        gemm_h<<<dim3(DIMC / 128, MBh, 1), 256, GEMM_SMEM, s>>>(
            mlph_h, fc2wh, fc2_b, x2_h, outx_h, nullptr,
            HROWS, DIMC, HIDDEN, HIDDEN, HIDDEN, DIMC, 1.0f, 0);
    }

    cudaEventRecord(eA, sA);
    cudaEventRecord(eB, sB);
    cudaStreamWaitEvent(0, eA, 0);
    cudaStreamWaitEvent(0, eB, 0);
}

// round 16
// speedup vs baseline: 1.1393x; 1.0021x over previous
#include <cuda_runtime.h>
#include <cuda_fp16.h>
#include <math.h>
#include <stdint.h>

// Problem constants
#define DIMC   768
#define NHEADS 12
#define HD     64
#define BATCH  16
#define SEQ    596
#define ROWS   (BATCH*SEQ)      // 9536
#define HBATCH (BATCH/2)
#define HROWS  (HBATCH*SEQ)     // 4768
#define QKVC   2304
#define HIDDEN 3072
#define CLSK   20

// ---------------- scratch ---------------------------------------------------------
__device__ __half g_h1h [ROWS*DIMC];
__device__ __half g_qkvh[ROWS*QKVC];
__device__ __half g_och [ROWS*DIMC];
__device__ __half g_mlph[ROWS*HIDDEN];
__device__ float  g_x2  [ROWS*DIMC];
__device__ __half g_qkvwh[QKVC*DIMC];
__device__ __half g_projwh[DIMC*DIMC];
__device__ __half g_fc1wh[HIDDEN*DIMC];
__device__ __half g_fc2wh[DIMC*HIDDEN];

// ---------------- fp32 -> fp16, vectorized ----------------------------------------
__global__ void f2h4(const float4* __restrict__ a, __half2* __restrict__ o, int n4) {
    int i = blockIdx.x * 256 + threadIdx.x;
    if (i < n4) {
        float4 v = a[i];
        o[2 * i]     = __floats2half2_rn(v.x, v.y);
        o[2 * i + 1] = __floats2half2_rn(v.z, v.w);
    }
}

// ---------------- LayerNorm: 192 thr/row, single pass, register-cached -------------
__global__ __launch_bounds__(192)
void ln_kernel(const float* __restrict__ x,
               const float* __restrict__ g,
               const float* __restrict__ b,
               __half* __restrict__ out) {
    int row = blockIdx.x;
    int t = threadIdx.x;
    const float4* xr = (const float4*)(x + (long long)row * DIMC);
    float4 v = xr[t];

    float s  = v.x + v.y + v.z + v.w;
    float s2 = v.x * v.x + v.y * v.y + v.z * v.z + v.w * v.w;
    #pragma unroll
    for (int o = 16; o; o >>= 1) {
        s  += __shfl_xor_sync(0xffffffffu, s,  o);
        s2 += __shfl_xor_sync(0xffffffffu, s2, o);
    }
    __shared__ float rs[6], rs2[6];
    int wid = t >> 5, lid = t & 31;
    if (lid == 0) { rs[wid] = s; rs2[wid] = s2; }
    __syncthreads();
    if (t < 32) {
        float a  = (t < 6) ? rs[t]  : 0.f;
        float a2 = (t < 6) ? rs2[t] : 0.f;
        #pragma unroll
        for (int o = 4; o; o >>= 1) {
            a  += __shfl_xor_sync(0xffffffffu, a,  o);
            a2 += __shfl_xor_sync(0xffffffffu, a2, o);
        }
        if (t == 0) { rs[0] = a; rs2[0] = a2; }
    }
    __syncthreads();
    float mean = rs[0] * (1.0f / DIMC);
    float var  = rs2[0] * (1.0f / DIMC) - mean * mean;
    float inv  = rsqrtf(var + 1e-5f);

    float4 gg = *(const float4*)(g + t * 4);
    float4 bb = *(const float4*)(b + t * 4);
    float o0 = (v.x - mean) * inv * gg.x + bb.x;
    float o1 = (v.y - mean) * inv * gg.y + bb.y;
    float o2 = (v.z - mean) * inv * gg.z + bb.z;
    float o3 = (v.w - mean) * inv * gg.w + bb.w;
    __half2 h01 = __floats2half2_rn(o0, o1);
    __half2 h23 = __floats2half2_rn(o2, o3);
    uint2 pk = make_uint2(*(uint32_t*)&h01, *(uint32_t*)&h23);
    *(uint2*)(out + (long long)row * DIMC + t * 4) = pk;
}

// ---------------- shared helpers ---------------------------------------------------
#define SROWB 144

__device__ __forceinline__ void mma16(float* c, const uint32_t* a, const uint32_t* b) {
    asm volatile(
        "mma.sync.aligned.m16n8k16.row.col.f32.f16.f16.f32 "
        "{%0,%1,%2,%3}, {%4,%5,%6,%7}, {%8,%9}, {%0,%1,%2,%3};"
        : "+f"(c[0]), "+f"(c[1]), "+f"(c[2]), "+f"(c[3])
        : "r"(a[0]), "r"(a[1]), "r"(a[2]), "r"(a[3]), "r"(b[0]), "r"(b[1]));
}
__device__ __forceinline__ void cpa16(uint32_t dst, const void* src, bool pred) {
    unsigned ssz = pred ? 16u : 0u;
    asm volatile("cp.async.cg.shared.global [%0], [%1], 16, %2;"
                 :: "r"(dst), "l"(src), "r"(ssz));
}
__device__ __forceinline__ void cp_commit() { asm volatile("cp.async.commit_group;"); }

__device__ __forceinline__ void ldmA(uint32_t* a, uint32_t base, int m0, int kb, int lane) {
    uint32_t addr = base + (uint32_t)(m0 + (lane & 15)) * SROWB
                  + (uint32_t)(kb + (lane >> 4) * 8) * 2;
    asm volatile("ldmatrix.sync.aligned.m8n8.x4.shared.b16 {%0,%1,%2,%3}, [%4];"
                 : "=r"(a[0]), "=r"(a[1]), "=r"(a[2]), "=r"(a[3]) : "r"(addr));
}
__device__ __forceinline__ void ldmB2(uint32_t* b, uint32_t base, int n0, int kb, int lane) {
    uint32_t addr = base + (uint32_t)(n0 + (lane & 7) + ((lane >> 4) * 8)) * SROWB
                  + (uint32_t)(kb + ((lane >> 3) & 1) * 8) * 2;
    asm volatile("ldmatrix.sync.aligned.m8n8.x4.shared.b16 {%0,%1,%2,%3}, [%4];"
                 : "=r"(b[0]), "=r"(b[1]), "=r"(b[2]), "=r"(b[3]) : "r"(addr));
}
__device__ __forceinline__ void ldm4(uint32_t* r, uint32_t addr) {
    asm volatile("ldmatrix.sync.aligned.m8n8.x4.shared.b16 {%0,%1,%2,%3}, [%4];"
                 : "=r"(r[0]), "=r"(r[1]), "=r"(r[2]), "=r"(r[3]) : "r"(addr));
}
__device__ __forceinline__ void ldm4t(uint32_t* r, uint32_t addr) {
    asm volatile("ldmatrix.sync.aligned.m8n8.x4.trans.shared.b16 {%0,%1,%2,%3}, [%4];"
                 : "=r"(r[0]), "=r"(r[1]), "=r"(r[2]), "=r"(r[3]) : "r"(addr));
}

// ---------------- fused attention: QK^T -> split softmax -> AV ---------------------
#define QS 64
#define SRS 2560
#define KV_STG (128*SROWB)
#define SM_Q  0
#define SM_KV 9216
#define SM_S  46080
#define ATTN_SMEM (SM_S + QS*SRS)     // 209920

__global__ __launch_bounds__(256, 1)
void attn_fused(const __half* __restrict__ qkvh,
                float* __restrict__ out_w,
                __half* __restrict__ och) {
    extern __shared__ __align__(16) char sh[];
    uint32_t shb = (uint32_t)__cvta_generic_to_shared(sh);

    int z = blockIdx.y;
    int b = z / NHEADS, h = z % NHEADS;
    int q0 = blockIdx.x * QS;
    int tid = threadIdx.x, warp = tid >> 5, lane = tid & 31;
    int wm = warp >> 1, wn = warp & 1;
    int group = lane >> 2, tg = lane & 3;

    const __half* Qg = qkvh + (long long)(b * SEQ) * QKVC + h * HD;
    const __half* Kg = Qg + DIMC;
    const __half* Vg = Qg + 2 * DIMC;

    #pragma unroll
    for (int t = 0; t < 2; t++) {
        int i = tid + t * 256;
        int r = i >> 3, c = i & 7;
        int gq = q0 + r;
        cpa16(shb + SM_Q + r * SROWB + c * 16, Qg + (long long)gq * QKVC + c * 8, gq < SEQ);
    }
    #pragma unroll
    for (int t = 0; t < 4; t++) {
        int i = tid + t * 256;
        int r = i >> 3, c = i & 7;
        cpa16(shb + SM_KV + r * SROWB + c * 16, Kg + (long long)r * QKVC + c * 8, r < SEQ);
    }
    cp_commit();

    uint32_t aq[4][4];

    for (int jb = 0; jb < 5; jb++) {
        if (jb < 4) {
            int s = (jb + 1) & 1;
            int kb0 = (jb + 1) * 128;
            #pragma unroll
            for (int t = 0; t < 4; t++) {
                int i = tid + t * 256;
                int r = i >> 3, c = i & 7;
                int gk = kb0 + r;
                cpa16(shb + SM_KV + s * KV_STG + r * SROWB + c * 16,
                      Kg + (long long)gk * QKVC + c * 8, gk < SEQ);
            }
            cp_commit();
            asm volatile("cp.async.wait_group 1;");
        } else {
            asm volatile("cp.async.wait_group 0;");
        }
        __syncthreads();
        if (jb == 0) {
            #pragma unroll
            for (int ks = 0; ks < 4; ks++)
                ldmA(aq[ks], shb + SM_Q, wm * 16, ks * 16, lane);
        }
        float acc[8][4];
        #pragma unroll
        for (int i = 0; i < 8; i++)
            #pragma unroll
            for (int r = 0; r < 4; r++) acc[i][r] = 0.f;

        uint32_t kbase = shb + SM_KV + (jb & 1) * KV_STG;
        #pragma unroll
        for (int ks = 0; ks < 4; ks++) {
            uint32_t bfr[8][2];
            #pragma unroll
            for (int nt = 0; nt < 8; nt += 2) {
                uint32_t bb[4];
                ldmB2(bb, kbase, wn * 64 + nt * 8, ks * 16, lane);
                bfr[nt][0] = bb[0]; bfr[nt][1] = bb[1];
                bfr[nt + 1][0] = bb[2]; bfr[nt + 1][1] = bb[3];
            }
            #pragma unroll
            for (int nt = 0; nt < 8; nt++) mma16(acc[nt], aq[ks], bfr[nt]);
        }
        #pragma unroll
        for (int nt = 0; nt < 8; nt++) {
            int col = jb * 128 + wn * 64 + nt * 8 + tg * 2;
            #pragma unroll
            for (int hf = 0; hf < 2; hf++) {
                int row = wm * 16 + group + hf * 8;
                float2 v = make_float2(acc[nt][hf * 2] * 0.125f, acc[nt][hf * 2 + 1] * 0.125f);
                *(float2*)(sh + SM_S + row * SRS + col * 4) = v;
            }
        }
        __syncthreads();
    }

    #pragma unroll
    for (int t = 0; t < 4; t++) {
        int i = tid + t * 256;
        int r = i >> 3, c = i & 7;
        cpa16(shb + SM_KV + r * SROWB + c * 16, Vg + (long long)r * QKVC + c * 8, r < SEQ);
    }
    cp_commit();

    #pragma unroll 1
    for (int rr = 0; rr < 8; rr++) {
        int row = warp * 8 + rr;
        const char* srow = sh + SM_S + row * SRS;
        float2 v[10];
        #pragma unroll
        for (int j = 0; j < 10; j++) {
            int c0 = j * 64 + lane * 2;
            float2 f = *(const float2*)(srow + c0 * 4);
            v[j].x = (c0     < SEQ) ? f.x : -1e30f;
            v[j].y = (c0 + 1 < SEQ) ? f.y : -1e30f;
        }
        bool in0 = lane < 10;

        float m0 = in0 ? fmaxf(v[0].x, v[0].y) : -1e30f;
        float m1 = in0 ? -1e30f : fmaxf(v[0].x, v[0].y);
        #pragma unroll
        for (int j = 1; j < 10; j++) m1 = fmaxf(m1, fmaxf(v[j].x, v[j].y));
        #pragma unroll
        for (int o = 16; o; o >>= 1) {
            m0 = fmaxf(m0, __shfl_xor_sync(0xffffffffu, m0, o));
            m1 = fmaxf(m1, __shfl_xor_sync(0xffffffffu, m1, o));
        }

        float s0 = 0.f, s1 = 0.f;
        {
            float mm = in0 ? m0 : m1;
            float ex = __expf(v[0].x - mm);
            float ey = __expf(v[0].y - mm);
            v[0].x = ex; v[0].y = ey;
            if (in0) s0 += ex + ey; else s1 += ex + ey;
        }
        #pragma unroll
        for (int j = 1; j < 10; j++) {
            int c0 = j * 64 + lane * 2;
            float ex = (c0     < SEQ) ? __expf(v[j].x - m1) : 0.f;
            float ey = (c0 + 1 < SEQ) ? __expf(v[j].y - m1) : 0.f;
            v[j].x = ex; v[j].y = ey;
            s1 += ex + ey;
        }
        #pragma unroll
        for (int o = 16; o; o >>= 1) {
            s0 += __shfl_xor_sync(0xffffffffu, s0, o);
            s1 += __shfl_xor_sync(0xffffffffu, s1, o);
        }
        float r0 = 1.0f / s0, r1 = 1.0f / s1;

        int gq = q0 + row;
        bool qok = gq < SEQ;
        float* wrow = out_w + ((long long)z * SEQ + gq) * SEQ;
        __half* hrow = (__half*)(sh + SM_S + row * SRS + 16 * (row & 7));
        {
            float rr0 = in0 ? r0 : r1;
            float2 o2 = make_float2(v[0].x * rr0, v[0].y * rr0);
            if (qok) __stcs((float2*)(wrow + lane * 2), o2);
            *(__half2*)(hrow + lane * 2) = __floats2half2_rn(o2.x, o2.y);
        }
        #pragma unroll
        for (int j = 1; j < 10; j++) {
            int c0 = j * 64 + lane * 2;
            float2 o2 = make_float2(v[j].x * r1, v[j].y * r1);
            if (c0 + 1 < SEQ) {
                if (qok) __stcs((float2*)(wrow + c0), o2);
                *(__half2*)(hrow + c0) = __floats2half2_rn(o2.x, o2.y);
            } else if (c0 < SEQ) {
                if (qok) __stcs(wrow + c0, o2.x);
                hrow[c0] = __float2half_rn(o2.x);
            }
        }
        if (lane < 22) *(__half2*)(hrow + SEQ + lane * 2) = __half2half2(__float2half(0.f));
    }
    __syncthreads();

    float oacc[4][4];
    #pragma unroll
    for (int i = 0; i < 4; i++)
        #pragma unroll
        for (int r = 0; r < 4; r++) oacc[i][r] = 0.f;

    for (int vb = 0; vb < 5; vb++) {
        if (vb < 4) {
            int s = (vb + 1) & 1;
            int v0 = (vb + 1) * 128;
            #pragma unroll
            for (int t = 0; t < 4; t++) {
                int i = tid + t * 256;
                int r = i >> 3, c = i & 7;
                int gk = v0 + r;
                cpa16(shb + SM_KV + s * KV_STG + r * SROWB + c * 16,
                      Vg + (long long)gk * QKVC + c * 8, gk < SEQ);
            }
            cp_commit();
            asm volatile("cp.async.wait_group 1;");
        } else {
            asm volatile("cp.async.wait_group 0;");
        }
        __syncthreads();
        uint32_t vbase = shb + SM_KV + (vb & 1) * KV_STG;
        #pragma unroll
        for (int ks = 0; ks < 8; ks++) {
            uint32_t a[4];
            {
                int row = wm * 16 + (lane & 15);
                int kcol = vb * 128 + ks * 16 + (lane >> 4) * 8;
                ldm4(a, shb + SM_S + row * SRS + 16 * (row & 7) + kcol * 2);
            }
            uint32_t bfr[4][2];
            #pragma unroll
            for (int nt = 0; nt < 4; nt += 2) {
                int krow = ks * 16 + (lane & 15);
                int ncol = wn * 32 + nt * 8 + ((lane >> 4) << 3);
                uint32_t bb[4];
                ldm4t(bb, vbase + krow * SROWB + ncol * 2);
                bfr[nt][0] = bb[0]; bfr[nt][1] = bb[1];
                bfr[nt + 1][0] = bb[2]; bfr[nt + 1][1] = bb[3];
            }
            #pragma unroll
            for (int nt = 0; nt < 4; nt++) mma16(oacc[nt], a, bfr[nt]);
        }
        __syncthreads();
    }

    #pragma unroll
    for (int nt = 0; nt < 4; nt++) {
        int col = wn * 32 + nt * 8 + tg * 2;
        #pragma unroll
        for (int hf = 0; hf < 2; hf++) {
            int row = wm * 16 + group + hf * 8;
            int gq = q0 + row;
            if (gq < SEQ) {
                __half2 hv = __floats2half2_rn(oacc[nt][hf * 2], oacc[nt][hf * 2 + 1]);
                *(__half2*)(och + (long long)(b * SEQ + gq) * DIMC + h * HD + col) = hv;
            }
        }
    }
}

// ---------------- fp16 GEMM (TN): 128x128 tile, 256 thr, 2 CTA/SM, 3 stages --------
#define BK 64
#define NSTG 3
#define TILE_A (128*SROWB)
#define TILE_Bt (128*SROWB)
#define STG (TILE_A + TILE_Bt)
#define GEMM_SMEM (NSTG*STG)        // 110592

__global__ __launch_bounds__(256, 2)
void gemm_h(const __half* __restrict__ A, const __half* __restrict__ B,
            const float* __restrict__ bias, const float* __restrict__ res,
            float* __restrict__ Cf, __half* __restrict__ Ch,
            int M, int Nn, int K, int lda, int ldb, int ldc,
            float alpha, int act) {
    extern __shared__ __align__(16) char sh[];
    uint32_t shb = (uint32_t)__cvta_generic_to_shared(sh);

    int tid = threadIdx.x, warp = tid >> 5, lane = tid & 31;
    int wm = warp >> 2, wn = warp & 3;
    int group = lane >> 2, tg = lane & 3;
    int row0 = blockIdx.y * 128, col0 = blockIdx.x * 128;

    float acc[4][4][4];
    #pragma unroll
    for (int i = 0; i < 4; i++)
        #pragma unroll
        for (int j = 0; j < 4; j++)
            #pragma unroll
            for (int r = 0; r < 4; r++) acc[i][j][r] = 0.f;

    auto load_tiles = [&](int s, int k0) {
        uint32_t a0 = shb + s * STG;
        uint32_t b0 = a0 + TILE_A;
        #pragma unroll
        for (int t = 0; t < 4; t++) {
            int i = tid + t * 256;
            int r = i >> 3, c = i & 7;
            int gr = row0 + r;
            cpa16(a0 + r * SROWB + c * 16, A + (long long)gr * lda + k0 + c * 8, gr < M);
        }
        #pragma unroll
        for (int t = 0; t < 4; t++) {
            int i = tid + t * 256;
            int r = i >> 3, c = i & 7;
            int gn = col0 + r;
            cpa16(b0 + r * SROWB + c * 16, B + (long long)gn * ldb + k0 + c * 8, gn < Nn);
        }
    };

    auto compute = [&](int s) {
        uint32_t a0 = shb + s * STG;
        uint32_t b0 = a0 + TILE_A;
        #pragma unroll
        for (int ks = 0; ks < 4; ks++) {
            int kb = ks * 16;
            uint32_t a[4][4], b[4][2];
            #pragma unroll
            for (int mt = 0; mt < 4; mt++)
                ldmA(a[mt], a0, wm * 64 + mt * 16, kb, lane);
            #pragma unroll
            for (int nt = 0; nt < 4; nt += 2) {
                uint32_t bb[4];
                ldmB2(bb, b0, wn * 32 + nt * 8, kb, lane);
                b[nt][0] = bb[0]; b[nt][1] = bb[1];
                b[nt + 1][0] = bb[2]; b[nt + 1][1] = bb[3];
            }
            #pragma unroll
            for (int mt = 0; mt < 4; mt++)
                #pragma unroll
                for (int nt = 0; nt < 4; nt++)
                    mma16(acc[mt][nt], a[mt], b[nt]);
        }
    };

    int nT = K / BK;
    #pragma unroll
    for (int s = 0; s < NSTG - 1; s++) {
        if (s < nT) load_tiles(s, s * BK);
        cp_commit();
    }
    for (int t = 0; t < nT; t++) {
        asm volatile("cp.async.wait_group %0;" :: "n"(NSTG - 2));
        __syncthreads();
        int pf = t + NSTG - 1;
        if (pf < nT) load_tiles(pf % NSTG, pf * BK);
        cp_commit();
        compute(t % NSTG);
    }

    #pragma unroll
    for (int mt = 0; mt < 4; mt++) {
        #pragma unroll
        for (int nt = 0; nt < 4; nt++) {
            int gc = col0 + wn * 32 + nt * 8 + tg * 2;
            if (gc >= Nn) continue;
            float bx = 0.f, by = 0.f;
            if (bias) { bx = bias[gc]; by = bias[gc + 1]; }
            #pragma unroll
            for (int hf = 0; hf < 2; hf++) {
                int gm = row0 + wm * 64 + mt * 16 + group + hf * 8;
                if (gm >= M) continue;
                float v0 = acc[mt][nt][hf * 2]     * alpha + bx;
                float v1 = acc[mt][nt][hf * 2 + 1] * alpha + by;
                if (act == 1) {
                    v0 = 0.5f * v0 * (1.0f + erff(v0 * 0.70710678118654752f));
                    v1 = 0.5f * v1 * (1.0f + erff(v1 * 0.70710678118654752f));
                }
                if (res) {
                    float2 rr = *(const float2*)(res + (long long)gm * ldc + gc);
                    v0 += rr.x; v1 += rr.y;
                }
                if (Cf) *(float2*)(Cf + (long long)gm * ldc + gc) = make_float2(v0, v1);
                if (Ch) *(__half2*)(Ch + (long long)gm * ldc + gc) =
                            __floats2half2_rn(v0, v1);
            }
        }
    }
}

// ---------------- host-side orchestration -------------------------------------------
extern "C" void kernel_launch(void* const* d_in, const int* in_sizes, int n_in,
                              void* d_out, int out_size) {
    const float* x      = (const float*)d_in[0];
    const float* qkv_w  = (const float*)d_in[1];
    const float* qkv_b  = (const float*)d_in[2];
    const float* proj_w = (const float*)d_in[3];
    const float* proj_b = (const float*)d_in[4];
    const float* ln1_g  = (const float*)d_in[5];
    const float* ln1_b  = (const float*)d_in[6];
    const float* ln2_g  = (const float*)d_in[7];
    const float* ln2_b  = (const float*)d_in[8];
    const float* fc1_w  = (const float*)d_in[9];
    const float* fc1_b  = (const float*)d_in[10];
    const float* fc2_w  = (const float*)d_in[11];
    const float* fc2_b  = (const float*)d_in[12];

    float* out_x = (float*)d_out;
    float* out_w = out_x + (long long)ROWS * DIMC;

    __half *h1h, *qkvh, *och, *mlph, *qkvwh, *projwh, *fc1wh, *fc2wh;
    float* x2;
    cudaGetSymbolAddress((void**)&h1h,   g_h1h);
    cudaGetSymbolAddress((void**)&qkvh,  g_qkvh);
    cudaGetSymbolAddress((void**)&och,   g_och);
    cudaGetSymbolAddress((void**)&mlph,  g_mlph);
    cudaGetSymbolAddress((void**)&x2,    g_x2);
    cudaGetSymbolAddress((void**)&qkvwh, g_qkvwh);
    cudaGetSymbolAddress((void**)&projwh,g_projwh);
    cudaGetSymbolAddress((void**)&fc1wh, g_fc1wh);
    cudaGetSymbolAddress((void**)&fc2wh, g_fc2wh);

    cudaFuncSetAttribute((const void*)gemm_h,
                         cudaFuncAttributeMaxDynamicSharedMemorySize, GEMM_SMEM);
    cudaFuncSetAttribute((const void*)attn_fused,
                         cudaFuncAttributeMaxDynamicSharedMemorySize, ATTN_SMEM);

    static cudaStream_t sA = nullptr, sB = nullptr, sW = nullptr;
    static cudaEvent_t e0 = nullptr, eWq = nullptr, eW = nullptr, eA = nullptr, eB = nullptr;
    if (!sA) {
        cudaStreamCreateWithFlags(&sA, cudaStreamNonBlocking);
        cudaStreamCreateWithFlags(&sB, cudaStreamNonBlocking);
        cudaStreamCreateWithFlags(&sW, cudaStreamNonBlocking);
        cudaEventCreateWithFlags(&e0,  cudaEventDisableTiming);
        cudaEventCreateWithFlags(&eWq, cudaEventDisableTiming);
        cudaEventCreateWithFlags(&eW,  cudaEventDisableTiming);
        cudaEventCreateWithFlags(&eA,  cudaEventDisableTiming);
        cudaEventCreateWithFlags(&eB,  cudaEventDisableTiming);
    }

    cudaEventRecord(e0, 0);
    cudaStreamWaitEvent(sW, e0, 0);
    cudaStreamWaitEvent(sA, e0, 0);
    cudaStreamWaitEvent(sB, e0, 0);

    // qkv weights first: QKV GEMM gates only on eWq
    f2h4<<<(QKVC * DIMC / 4 + 255) / 256, 256, 0, sW>>>((const float4*)qkv_w, (__half2*)qkvwh, QKVC * DIMC / 4);
    cudaEventRecord(eWq, sW);
    // remaining weights finish in the shadow of QKV+attention
    f2h4<<<(DIMC * DIMC / 4 + 255) / 256, 256, 0, sW>>>((const float4*)proj_w, (__half2*)projwh, DIMC * DIMC / 4);
    f2h4<<<(HIDDEN * DIMC / 4 + 255) / 256, 256, 0, sW>>>((const float4*)fc1_w, (__half2*)fc1wh, HIDDEN * DIMC / 4);
    f2h4<<<(DIMC * HIDDEN / 4 + 255) / 256, 256, 0, sW>>>((const float4*)fc2_w, (__half2*)fc2wh, DIMC * HIDDEN / 4);
    cudaEventRecord(eW, sW);

    const int MBh = (HROWS + 127) / 128;   // 38

    for (int hf = 0; hf < 2; hf++) {
        cudaStream_t s = hf ? sB : sA;
        long long r0 = (long long)hf * HROWS;
        const float* xh   = x   + r0 * DIMC;
        __half* h1h_h     = h1h + r0 * DIMC;
        __half* qkvh_h    = qkvh + r0 * QKVC;
        __half* och_h     = och + r0 * DIMC;
        __half* mlph_h    = mlph + r0 * HIDDEN;
        float*  x2_h      = x2  + r0 * DIMC;
        float*  outx_h    = out_x + r0 * DIMC;
        float*  outw_h    = out_w + (long long)hf * HBATCH * NHEADS * SEQ * SEQ;

        ln_kernel<<<HROWS, 192, 0, s>>>(xh, ln1_g, ln1_b, h1h_h);
        cudaStreamWaitEvent(s, eWq, 0);   // only qkv weights needed here

        gemm_h<<<dim3(QKVC / 128, MBh, 1), 256, GEMM_SMEM, s>>>(
            h1h_h, qkvwh, qkv_b, nullptr, nullptr, qkvh_h,
            HROWS, QKVC, DIMC, DIMC, DIMC, QKVC, 1.0f, 0);

        attn_fused<<<dim3((SEQ + QS - 1) / QS, HBATCH * NHEADS), 256, ATTN_SMEM, s>>>(
            qkvh_h, outw_h, och_h);

        cudaStreamWaitEvent(s, eW, 0);    // proj/fc1/fc2 weights ready by now

        gemm_h<<<dim3(DIMC / 128, MBh, 1), 256, GEMM_SMEM, s>>>(
            och_h, projwh, proj_b, xh, x2_h, nullptr,
            HROWS, DIMC, DIMC, DIMC, DIMC, DIMC, 1.0f, 0);

        ln_kernel<<<HROWS, 192, 0, s>>>(x2_h, ln2_g, ln2_b, h1h_h);

        gemm_h<<<dim3(HIDDEN / 128, MBh, 1), 256, GEMM_SMEM, s>>>(
            h1h_h, fc1wh, fc1_b, nullptr, nullptr, mlph_h,
            HROWS, HIDDEN, DIMC, DIMC, DIMC, HIDDEN, 1.0f, 1);

        gemm_h<<<dim3(DIMC / 128, MBh, 1), 256, GEMM_SMEM, s>>>(
            mlph_h, fc2wh, fc2_b, x2_h, outx_h, nullptr,
            HROWS, DIMC, HIDDEN, HIDDEN, HIDDEN, DIMC, 1.0f, 0);
    }

    cudaEventRecord(eA, sA);
    cudaEventRecord(eB, sB);
    cudaStreamWaitEvent(0, eA, 0);
    cudaStreamWaitEvent(0, eB, 0);
}

// round 17
// speedup vs baseline: 1.1493x; 1.0088x over previous
#include <cuda_runtime.h>
#include <cuda_fp16.h>
#include <math.h>
#include <stdint.h>

// Problem constants
#define DIMC   768
#define NHEADS 12
#define HD     64
#define BATCH  16
#define SEQ    596
#define ROWS   (BATCH*SEQ)      // 9536
#define HBATCH (BATCH/2)
#define HROWS  (HBATCH*SEQ)     // 4768
#define QKVC   2304
#define HIDDEN 3072
#define CLSK   20

// ---------------- scratch ---------------------------------------------------------
__device__ __half g_h1h [ROWS*DIMC];
__device__ __half g_qkvh[ROWS*QKVC];
__device__ __half g_och [ROWS*DIMC];
__device__ __half g_mlph[ROWS*HIDDEN];
__device__ float  g_x2  [ROWS*DIMC];
__device__ __half g_qkvwh[QKVC*DIMC];
__device__ __half g_projwh[DIMC*DIMC];
__device__ __half g_fc1wh[HIDDEN*DIMC];
__device__ __half g_fc2wh[DIMC*HIDDEN];

// ---------------- fp32 -> fp16, vectorized ----------------------------------------
__global__ void f2h4(const float4* __restrict__ a, __half2* __restrict__ o, int n4) {
    int i = blockIdx.x * 256 + threadIdx.x;
    if (i < n4) {
        float4 v = a[i];
        o[2 * i]     = __floats2half2_rn(v.x, v.y);
        o[2 * i + 1] = __floats2half2_rn(v.z, v.w);
    }
}

// ---------------- LayerNorm: 192 thr/row, single pass, register-cached -------------
__global__ __launch_bounds__(192)
void ln_kernel(const float* __restrict__ x,
               const float* __restrict__ g,
               const float* __restrict__ b,
               __half* __restrict__ out) {
    int row = blockIdx.x;
    int t = threadIdx.x;
    const float4* xr = (const float4*)(x + (long long)row * DIMC);
    float4 v = xr[t];

    float s  = v.x + v.y + v.z + v.w;
    float s2 = v.x * v.x + v.y * v.y + v.z * v.z + v.w * v.w;
    #pragma unroll
    for (int o = 16; o; o >>= 1) {
        s  += __shfl_xor_sync(0xffffffffu, s,  o);
        s2 += __shfl_xor_sync(0xffffffffu, s2, o);
    }
    __shared__ float rs[6], rs2[6];
    int wid = t >> 5, lid = t & 31;
    if (lid == 0) { rs[wid] = s; rs2[wid] = s2; }
    __syncthreads();
    if (t < 32) {
        float a  = (t < 6) ? rs[t]  : 0.f;
        float a2 = (t < 6) ? rs2[t] : 0.f;
        #pragma unroll
        for (int o = 4; o; o >>= 1) {
            a  += __shfl_xor_sync(0xffffffffu, a,  o);
            a2 += __shfl_xor_sync(0xffffffffu, a2, o);
        }
        if (t == 0) { rs[0] = a; rs2[0] = a2; }
    }
    __syncthreads();
    float mean = rs[0] * (1.0f / DIMC);
    float var  = rs2[0] * (1.0f / DIMC) - mean * mean;
    float inv  = rsqrtf(var + 1e-5f);

    float4 gg = *(const float4*)(g + t * 4);
    float4 bb = *(const float4*)(b + t * 4);
    float o0 = (v.x - mean) * inv * gg.x + bb.x;
    float o1 = (v.y - mean) * inv * gg.y + bb.y;
    float o2 = (v.z - mean) * inv * gg.z + bb.z;
    float o3 = (v.w - mean) * inv * gg.w + bb.w;
    __half2 h01 = __floats2half2_rn(o0, o1);
    __half2 h23 = __floats2half2_rn(o2, o3);
    uint2 pk = make_uint2(*(uint32_t*)&h01, *(uint32_t*)&h23);
    *(uint2*)(out + (long long)row * DIMC + t * 4) = pk;
}

// ---------------- shared helpers ---------------------------------------------------
#define SROWB 144

__device__ __forceinline__ void mma16(float* c, const uint32_t* a, const uint32_t* b) {
    asm volatile(
        "mma.sync.aligned.m16n8k16.row.col.f32.f16.f16.f32 "
        "{%0,%1,%2,%3}, {%4,%5,%6,%7}, {%8,%9}, {%0,%1,%2,%3};"
        : "+f"(c[0]), "+f"(c[1]), "+f"(c[2]), "+f"(c[3])
        : "r"(a[0]), "r"(a[1]), "r"(a[2]), "r"(a[3]), "r"(b[0]), "r"(b[1]));
}
__device__ __forceinline__ void cpa16(uint32_t dst, const void* src, bool pred) {
    unsigned ssz = pred ? 16u : 0u;
    asm volatile("cp.async.cg.shared.global [%0], [%1], 16, %2;"
                 :: "r"(dst), "l"(src), "r"(ssz));
}
__device__ __forceinline__ void cp_commit() { asm volatile("cp.async.commit_group;"); }

__device__ __forceinline__ void ldmA(uint32_t* a, uint32_t base, int m0, int kb, int lane) {
    uint32_t addr = base + (uint32_t)(m0 + (lane & 15)) * SROWB
                  + (uint32_t)(kb + (lane >> 4) * 8) * 2;
    asm volatile("ldmatrix.sync.aligned.m8n8.x4.shared.b16 {%0,%1,%2,%3}, [%4];"
                 : "=r"(a[0]), "=r"(a[1]), "=r"(a[2]), "=r"(a[3]) : "r"(addr));
}
__device__ __forceinline__ void ldmB2(uint32_t* b, uint32_t base, int n0, int kb, int lane) {
    uint32_t addr = base + (uint32_t)(n0 + (lane & 7) + ((lane >> 4) * 8)) * SROWB
                  + (uint32_t)(kb + ((lane >> 3) & 1) * 8) * 2;
    asm volatile("ldmatrix.sync.aligned.m8n8.x4.shared.b16 {%0,%1,%2,%3}, [%4];"
                 : "=r"(b[0]), "=r"(b[1]), "=r"(b[2]), "=r"(b[3]) : "r"(addr));
}
__device__ __forceinline__ void ldm4(uint32_t* r, uint32_t addr) {
    asm volatile("ldmatrix.sync.aligned.m8n8.x4.shared.b16 {%0,%1,%2,%3}, [%4];"
                 : "=r"(r[0]), "=r"(r[1]), "=r"(r[2]), "=r"(r[3]) : "r"(addr));
}
__device__ __forceinline__ void ldm4t(uint32_t* r, uint32_t addr) {
    asm volatile("ldmatrix.sync.aligned.m8n8.x4.trans.shared.b16 {%0,%1,%2,%3}, [%4];"
                 : "=r"(r[0]), "=r"(r[1]), "=r"(r[2]), "=r"(r[3]) : "r"(addr));
}

// ---------------- fused attention: QK^T -> split softmax -> AV ---------------------
#define QS 64
#define SRS 2560
#define KV_STG (128*SROWB)
#define SM_Q  0
#define SM_KV 9216
#define SM_S  46080
#define ATTN_SMEM (SM_S + QS*SRS)     // 209920

__global__ __launch_bounds__(256, 1)
void attn_fused(const __half* __restrict__ qkvh,
                float* __restrict__ out_w,
                __half* __restrict__ och) {
    extern __shared__ __align__(16) char sh[];
    uint32_t shb = (uint32_t)__cvta_generic_to_shared(sh);

    int z = blockIdx.y;
    int b = z / NHEADS, h = z % NHEADS;
    int q0 = blockIdx.x * QS;
    int tid = threadIdx.x, warp = tid >> 5, lane = tid & 31;
    int wm = warp >> 1, wn = warp & 1;
    int group = lane >> 2, tg = lane & 3;

    const __half* Qg = qkvh + (long long)(b * SEQ) * QKVC + h * HD;
    const __half* Kg = Qg + DIMC;
    const __half* Vg = Qg + 2 * DIMC;

    #pragma unroll
    for (int t = 0; t < 2; t++) {
        int i = tid + t * 256;
        int r = i >> 3, c = i & 7;
        int gq = q0 + r;
        cpa16(shb + SM_Q + r * SROWB + c * 16, Qg + (long long)gq * QKVC + c * 8, gq < SEQ);
    }
    #pragma unroll
    for (int t = 0; t < 4; t++) {
        int i = tid + t * 256;
        int r = i >> 3, c = i & 7;
        cpa16(shb + SM_KV + r * SROWB + c * 16, Kg + (long long)r * QKVC + c * 8, r < SEQ);
    }
    cp_commit();

    uint32_t aq[4][4];

    for (int jb = 0; jb < 5; jb++) {
        if (jb < 4) {
            int s = (jb + 1) & 1;
            int kb0 = (jb + 1) * 128;
            #pragma unroll
            for (int t = 0; t < 4; t++) {
                int i = tid + t * 256;
                int r = i >> 3, c = i & 7;
                int gk = kb0 + r;
                cpa16(shb + SM_KV + s * KV_STG + r * SROWB + c * 16,
                      Kg + (long long)gk * QKVC + c * 8, gk < SEQ);
            }
            cp_commit();
            asm volatile("cp.async.wait_group 1;");
        } else {
            asm volatile("cp.async.wait_group 0;");
        }
        __syncthreads();
        if (jb == 0) {
            #pragma unroll
            for (int ks = 0; ks < 4; ks++)
                ldmA(aq[ks], shb + SM_Q, wm * 16, ks * 16, lane);
        }
        float acc[8][4];
        #pragma unroll
        for (int i = 0; i < 8; i++)
            #pragma unroll
            for (int r = 0; r < 4; r++) acc[i][r] = 0.f;

        uint32_t kbase = shb + SM_KV + (jb & 1) * KV_STG;
        #pragma unroll
        for (int ks = 0; ks < 4; ks++) {
            uint32_t bfr[8][2];
            #pragma unroll
            for (int nt = 0; nt < 8; nt += 2) {
                uint32_t bb[4];
                ldmB2(bb, kbase, wn * 64 + nt * 8, ks * 16, lane);
                bfr[nt][0] = bb[0]; bfr[nt][1] = bb[1];
                bfr[nt + 1][0] = bb[2]; bfr[nt + 1][1] = bb[3];
            }
            #pragma unroll
            for (int nt = 0; nt < 8; nt++) mma16(acc[nt], aq[ks], bfr[nt]);
        }
        #pragma unroll
        for (int nt = 0; nt < 8; nt++) {
            int col = jb * 128 + wn * 64 + nt * 8 + tg * 2;
            #pragma unroll
            for (int hf = 0; hf < 2; hf++) {
                int row = wm * 16 + group + hf * 8;
                float2 v = make_float2(acc[nt][hf * 2] * 0.125f, acc[nt][hf * 2 + 1] * 0.125f);
                *(float2*)(sh + SM_S + row * SRS + col * 4) = v;
            }
        }
        __syncthreads();
    }

    #pragma unroll
    for (int t = 0; t < 4; t++) {
        int i = tid + t * 256;
        int r = i >> 3, c = i & 7;
        cpa16(shb + SM_KV + r * SROWB + c * 16, Vg + (long long)r * QKVC + c * 8, r < SEQ);
    }
    cp_commit();

    // ---------------- phase 2: split softmax (lane owns column QUADS) -------------
    // c0 = j*128 + lane*4, j in [0,5). Segment 0 = cols [0,20) = j==0, lane<5.
    // SEQ % 4 == 0 and CLSK % 4 == 0, so all guards are whole-quad.
    #pragma unroll 1
    for (int rr = 0; rr < 8; rr++) {
        int row = warp * 8 + rr;
        const char* srow = sh + SM_S + row * SRS;
        float4 v[5];
        #pragma unroll
        for (int j = 0; j < 5; j++) {
            int c0 = j * 128 + lane * 4;
            if (c0 < SEQ) {
                v[j] = *(const float4*)(srow + c0 * 4);
            } else {
                v[j] = make_float4(-1e30f, -1e30f, -1e30f, -1e30f);
            }
        }
        bool in0 = lane < 5;   // quad fully inside [0,CLSK) when j==0

        float q0m = fmaxf(fmaxf(v[0].x, v[0].y), fmaxf(v[0].z, v[0].w));
        float m0 = in0 ? q0m : -1e30f;
        float m1 = in0 ? -1e30f : q0m;
        #pragma unroll
        for (int j = 1; j < 5; j++)
            m1 = fmaxf(m1, fmaxf(fmaxf(v[j].x, v[j].y), fmaxf(v[j].z, v[j].w)));
        #pragma unroll
        for (int o = 16; o; o >>= 1) {
            m0 = fmaxf(m0, __shfl_xor_sync(0xffffffffu, m0, o));
            m1 = fmaxf(m1, __shfl_xor_sync(0xffffffffu, m1, o));
        }

        float s0 = 0.f, s1 = 0.f;
        {
            float mm = in0 ? m0 : m1;
            v[0].x = __expf(v[0].x - mm);
            v[0].y = __expf(v[0].y - mm);
            v[0].z = __expf(v[0].z - mm);
            v[0].w = __expf(v[0].w - mm);
            float qs = v[0].x + v[0].y + v[0].z + v[0].w;
            if (in0) s0 += qs; else s1 += qs;
        }
        #pragma unroll
        for (int j = 1; j < 5; j++) {
            int c0 = j * 128 + lane * 4;
            if (c0 < SEQ) {
                v[j].x = __expf(v[j].x - m1);
                v[j].y = __expf(v[j].y - m1);
                v[j].z = __expf(v[j].z - m1);
                v[j].w = __expf(v[j].w - m1);
                s1 += v[j].x + v[j].y + v[j].z + v[j].w;
            }
        }
        #pragma unroll
        for (int o = 16; o; o >>= 1) {
            s0 += __shfl_xor_sync(0xffffffffu, s0, o);
            s1 += __shfl_xor_sync(0xffffffffu, s1, o);
        }
        float r0 = 1.0f / s0, r1 = 1.0f / s1;

        int gq = q0 + row;
        bool qok = gq < SEQ;
        float* wrow = out_w + ((long long)z * SEQ + gq) * SEQ;
        __half* hrow = (__half*)(sh + SM_S + row * SRS + 16 * (row & 7));
        {
            float rr0 = in0 ? r0 : r1;
            float4 o4 = make_float4(v[0].x * rr0, v[0].y * rr0, v[0].z * rr0, v[0].w * rr0);
            if (qok) __stcs((float4*)(wrow + lane * 4), o4);
            __half2 h01 = __floats2half2_rn(o4.x, o4.y);
            __half2 h23 = __floats2half2_rn(o4.z, o4.w);
            *(uint2*)(hrow + lane * 4) = make_uint2(*(uint32_t*)&h01, *(uint32_t*)&h23);
        }
        #pragma unroll
        for (int j = 1; j < 5; j++) {
            int c0 = j * 128 + lane * 4;
            if (c0 < SEQ) {
                float4 o4 = make_float4(v[j].x * r1, v[j].y * r1, v[j].z * r1, v[j].w * r1);
                if (qok) __stcs((float4*)(wrow + c0), o4);
                __half2 h01 = __floats2half2_rn(o4.x, o4.y);
                __half2 h23 = __floats2half2_rn(o4.z, o4.w);
                *(uint2*)(hrow + c0) = make_uint2(*(uint32_t*)&h01, *(uint32_t*)&h23);
            } else {
                // zero-pad fp16 cols [SEQ, 640)
                *(uint2*)(hrow + c0) = make_uint2(0u, 0u);
            }
        }
    }
    __syncthreads();

    float oacc[4][4];
    #pragma unroll
    for (int i = 0; i < 4; i++)
        #pragma unroll
        for (int r = 0; r < 4; r++) oacc[i][r] = 0.f;

    for (int vb = 0; vb < 5; vb++) {
        if (vb < 4) {
            int s = (vb + 1) & 1;
            int v0 = (vb + 1) * 128;
            #pragma unroll
            for (int t = 0; t < 4; t++) {
                int i = tid + t * 256;
                int r = i >> 3, c = i & 7;
                int gk = v0 + r;
                cpa16(shb + SM_KV + s * KV_STG + r * SROWB + c * 16,
                      Vg + (long long)gk * QKVC + c * 8, gk < SEQ);
            }
            cp_commit();
            asm volatile("cp.async.wait_group 1;");
        } else {
            asm volatile("cp.async.wait_group 0;");
        }
        __syncthreads();
        uint32_t vbase = shb + SM_KV + (vb & 1) * KV_STG;
        #pragma unroll
        for (int ks = 0; ks < 8; ks++) {
            uint32_t a[4];
            {
                int row = wm * 16 + (lane & 15);
                int kcol = vb * 128 + ks * 16 + (lane >> 4) * 8;
                ldm4(a, shb + SM_S + row * SRS + 16 * (row & 7) + kcol * 2);
            }
            uint32_t bfr[4][2];
            #pragma unroll
            for (int nt = 0; nt < 4; nt += 2) {
                int krow = ks * 16 + (lane & 15);
                int ncol = wn * 32 + nt * 8 + ((lane >> 4) << 3);
                uint32_t bb[4];
                ldm4t(bb, vbase + krow * SROWB + ncol * 2);
                bfr[nt][0] = bb[0]; bfr[nt][1] = bb[1];
                bfr[nt + 1][0] = bb[2]; bfr[nt + 1][1] = bb[3];
            }
            #pragma unroll
            for (int nt = 0; nt < 4; nt++) mma16(oacc[nt], a, bfr[nt]);
        }
        __syncthreads();
    }

    #pragma unroll
    for (int nt = 0; nt < 4; nt++) {
        int col = wn * 32 + nt * 8 + tg * 2;
        #pragma unroll
        for (int hf = 0; hf < 2; hf++) {
            int row = wm * 16 + group + hf * 8;
            int gq = q0 + row;
            if (gq < SEQ) {
                __half2 hv = __floats2half2_rn(oacc[nt][hf * 2], oacc[nt][hf * 2 + 1]);
                *(__half2*)(och + (long long)(b * SEQ + gq) * DIMC + h * HD + col) = hv;
            }
        }
    }
}

// ---------------- fp16 GEMM (TN): 128x128 tile, 256 thr, 2 CTA/SM, 3 stages --------
#define BK 64
#define NSTG 3
#define TILE_A (128*SROWB)
#define TILE_Bt (128*SROWB)
#define STG (TILE_A + TILE_Bt)
#define GEMM_SMEM (NSTG*STG)        // 110592

__global__ __launch_bounds__(256, 2)
void gemm_h(const __half* __restrict__ A, const __half* __restrict__ B,
            const float* __restrict__ bias, const float* __restrict__ res,
            float* __restrict__ Cf, __half* __restrict__ Ch,
            int M, int Nn, int K, int lda, int ldb, int ldc,
            float alpha, int act) {
    extern __shared__ __align__(16) char sh[];
    uint32_t shb = (uint32_t)__cvta_generic_to_shared(sh);

    int tid = threadIdx.x, warp = tid >> 5, lane = tid & 31;
    int wm = warp >> 2, wn = warp & 3;
    int group = lane >> 2, tg = lane & 3;
    int row0 = blockIdx.y * 128, col0 = blockIdx.x * 128;

    float acc[4][4][4];
    #pragma unroll
    for (int i = 0; i < 4; i++)
        #pragma unroll
        for (int j = 0; j < 4; j++)
            #pragma unroll
            for (int r = 0; r < 4; r++) acc[i][j][r] = 0.f;

    auto load_tiles = [&](int s, int k0) {
        uint32_t a0 = shb + s * STG;
        uint32_t b0 = a0 + TILE_A;
        #pragma unroll
        for (int t = 0; t < 4; t++) {
            int i = tid + t * 256;
            int r = i >> 3, c = i & 7;
            int gr = row0 + r;
            cpa16(a0 + r * SROWB + c * 16, A + (long long)gr * lda + k0 + c * 8, gr < M);
        }
        #pragma unroll
        for (int t = 0; t < 4; t++) {
            int i = tid + t * 256;
            int r = i >> 3, c = i & 7;
            int gn = col0 + r;
            cpa16(b0 + r * SROWB + c * 16, B + (long long)gn * ldb + k0 + c * 8, gn < Nn);
        }
    };

    auto compute = [&](int s) {
        uint32_t a0 = shb + s * STG;
        uint32_t b0 = a0 + TILE_A;
        #pragma unroll
        for (int ks = 0; ks < 4; ks++) {
            int kb = ks * 16;
            uint32_t a[4][4], b[4][2];
            #pragma unroll
            for (int mt = 0; mt < 4; mt++)
                ldmA(a[mt], a0, wm * 64 + mt * 16, kb, lane);
            #pragma unroll
            for (int nt = 0; nt < 4; nt += 2) {
                uint32_t bb[4];
                ldmB2(bb, b0, wn * 32 + nt * 8, kb, lane);
                b[nt][0] = bb[0]; b[nt][1] = bb[1];
                b[nt + 1][0] = bb[2]; b[nt + 1][1] = bb[3];
            }
            #pragma unroll
            for (int mt = 0; mt < 4; mt++)
                #pragma unroll
                for (int nt = 0; nt < 4; nt++)
                    mma16(acc[mt][nt], a[mt], b[nt]);
        }
    };

    int nT = K / BK;
    #pragma unroll
    for (int s = 0; s < NSTG - 1; s++) {
        if (s < nT) load_tiles(s, s * BK);
        cp_commit();
    }
    for (int t = 0; t < nT; t++) {
        asm volatile("cp.async.wait_group %0;" :: "n"(NSTG - 2));
        __syncthreads();
        int pf = t + NSTG - 1;
        if (pf < nT) load_tiles(pf % NSTG, pf * BK);
        cp_commit();
        compute(t % NSTG);
    }

    #pragma unroll
    for (int mt = 0; mt < 4; mt++) {
        #pragma unroll
        for (int nt = 0; nt < 4; nt++) {
            int gc = col0 + wn * 32 + nt * 8 + tg * 2;
            if (gc >= Nn) continue;
            float bx = 0.f, by = 0.f;
            if (bias) { bx = bias[gc]; by = bias[gc + 1]; }
            #pragma unroll
            for (int hf = 0; hf < 2; hf++) {
                int gm = row0 + wm * 64 + mt * 16 + group + hf * 8;
                if (gm >= M) continue;
                float v0 = acc[mt][nt][hf * 2]     * alpha + bx;
                float v1 = acc[mt][nt][hf * 2 + 1] * alpha + by;
                if (act == 1) {
                    v0 = 0.5f * v0 * (1.0f + erff(v0 * 0.70710678118654752f));
                    v1 = 0.5f * v1 * (1.0f + erff(v1 * 0.70710678118654752f));
                }
                if (res) {
                    float2 rr = *(const float2*)(res + (long long)gm * ldc + gc);
                    v0 += rr.x; v1 += rr.y;
                }
                if (Cf) *(float2*)(Cf + (long long)gm * ldc + gc) = make_float2(v0, v1);
                if (Ch) *(__half2*)(Ch + (long long)gm * ldc + gc) =
                            __floats2half2_rn(v0, v1);
            }
        }
    }
}

// ---------------- host-side orchestration -------------------------------------------
extern "C" void kernel_launch(void* const* d_in, const int* in_sizes, int n_in,
                              void* d_out, int out_size) {
    const float* x      = (const float*)d_in[0];
    const float* qkv_w  = (const float*)d_in[1];
    const float* qkv_b  = (const float*)d_in[2];
    const float* proj_w = (const float*)d_in[3];
    const float* proj_b = (const float*)d_in[4];
    const float* ln1_g  = (const float*)d_in[5];
    const float* ln1_b  = (const float*)d_in[6];
    const float* ln2_g  = (const float*)d_in[7];
    const float* ln2_b  = (const float*)d_in[8];
    const float* fc1_w  = (const float*)d_in[9];
    const float* fc1_b  = (const float*)d_in[10];
    const float* fc2_w  = (const float*)d_in[11];
    const float* fc2_b  = (const float*)d_in[12];

    float* out_x = (float*)d_out;
    float* out_w = out_x + (long long)ROWS * DIMC;

    __half *h1h, *qkvh, *och, *mlph, *qkvwh, *projwh, *fc1wh, *fc2wh;
    float* x2;
    cudaGetSymbolAddress((void**)&h1h,   g_h1h);
    cudaGetSymbolAddress((void**)&qkvh,  g_qkvh);
    cudaGetSymbolAddress((void**)&och,   g_och);
    cudaGetSymbolAddress((void**)&mlph,  g_mlph);
    cudaGetSymbolAddress((void**)&x2,    g_x2);
    cudaGetSymbolAddress((void**)&qkvwh, g_qkvwh);
    cudaGetSymbolAddress((void**)&projwh,g_projwh);
    cudaGetSymbolAddress((void**)&fc1wh, g_fc1wh);
    cudaGetSymbolAddress((void**)&fc2wh, g_fc2wh);

    cudaFuncSetAttribute((const void*)gemm_h,
                         cudaFuncAttributeMaxDynamicSharedMemorySize, GEMM_SMEM);
    cudaFuncSetAttribute((const void*)attn_fused,
                         cudaFuncAttributeMaxDynamicSharedMemorySize, ATTN_SMEM);

    static cudaStream_t sA = nullptr, sB = nullptr, sW = nullptr;
    static cudaEvent_t e0 = nullptr, eWq = nullptr, eW = nullptr, eA = nullptr, eB = nullptr;
    if (!sA) {
        cudaStreamCreateWithFlags(&sA, cudaStreamNonBlocking);
        cudaStreamCreateWithFlags(&sB, cudaStreamNonBlocking);
        cudaStreamCreateWithFlags(&sW, cudaStreamNonBlocking);
        cudaEventCreateWithFlags(&e0,  cudaEventDisableTiming);
        cudaEventCreateWithFlags(&eWq, cudaEventDisableTiming);
        cudaEventCreateWithFlags(&eW,  cudaEventDisableTiming);
        cudaEventCreateWithFlags(&eA,  cudaEventDisableTiming);
        cudaEventCreateWithFlags(&eB,  cudaEventDisableTiming);
    }

    cudaEventRecord(e0, 0);
    cudaStreamWaitEvent(sW, e0, 0);
    cudaStreamWaitEvent(sA, e0, 0);
    cudaStreamWaitEvent(sB, e0, 0);

    f2h4<<<(QKVC * DIMC / 4 + 255) / 256, 256, 0, sW>>>((const float4*)qkv_w, (__half2*)qkvwh, QKVC * DIMC / 4);
    cudaEventRecord(eWq, sW);
    f2h4<<<(DIMC * DIMC / 4 + 255) / 256, 256, 0, sW>>>((const float4*)proj_w, (__half2*)projwh, DIMC * DIMC / 4);
    f2h4<<<(HIDDEN * DIMC / 4 + 255) / 256, 256, 0, sW>>>((const float4*)fc1_w, (__half2*)fc1wh, HIDDEN * DIMC / 4);
    f2h4<<<(DIMC * HIDDEN / 4 + 255) / 256, 256, 0, sW>>>((const float4*)fc2_w, (__half2*)fc2wh, DIMC * HIDDEN / 4);
    cudaEventRecord(eW, sW);

    const int MBh = (HROWS + 127) / 128;   // 38

    for (int hf = 0; hf < 2; hf++) {
        cudaStream_t s = hf ? sB : sA;
        long long r0 = (long long)hf * HROWS;
        const float* xh   = x   + r0 * DIMC;
        __half* h1h_h     = h1h + r0 * DIMC;
        __half* qkvh_h    = qkvh + r0 * QKVC;
        __half* och_h     = och + r0 * DIMC;
        __half* mlph_h    = mlph + r0 * HIDDEN;
        float*  x2_h      = x2  + r0 * DIMC;
        float*  outx_h    = out_x + r0 * DIMC;
        float*  outw_h    = out_w + (long long)hf * HBATCH * NHEADS * SEQ * SEQ;

        ln_kernel<<<HROWS, 192, 0, s>>>(xh, ln1_g, ln1_b, h1h_h);
        cudaStreamWaitEvent(s, eWq, 0);

        gemm_h<<<dim3(QKVC / 128, MBh, 1), 256, GEMM_SMEM, s>>>(
            h1h_h, qkvwh, qkv_b, nullptr, nullptr, qkvh_h,
            HROWS, QKVC, DIMC, DIMC, DIMC, QKVC, 1.0f, 0);

        attn_fused<<<dim3((SEQ + QS - 1) / QS, HBATCH * NHEADS), 256, ATTN_SMEM, s>>>(
            qkvh_h, outw_h, och_h);

        cudaStreamWaitEvent(s, eW, 0);

        gemm_h<<<dim3(DIMC / 128, MBh, 1), 256, GEMM_SMEM, s>>>(
            och_h, projwh, proj_b, xh, x2_h, nullptr,
            HROWS, DIMC, DIMC, DIMC, DIMC, DIMC, 1.0f, 0);

        ln_kernel<<<HROWS, 192, 0, s>>>(x2_h, ln2_g, ln2_b, h1h_h);

        gemm_h<<<dim3(HIDDEN / 128, MBh, 1), 256, GEMM_SMEM, s>>>(
            h1h_h, fc1wh, fc1_b, nullptr, nullptr, mlph_h,
            HROWS, HIDDEN, DIMC, DIMC, DIMC, HIDDEN, 1.0f, 1);

        gemm_h<<<dim3(DIMC / 128, MBh, 1), 256, GEMM_SMEM, s>>>(
            mlph_h, fc2wh, fc2_b, x2_h, outx_h, nullptr,
            HROWS, DIMC, HIDDEN, HIDDEN, HIDDEN, DIMC, 1.0f, 0);
    }

    cudaEventRecord(eA, sA);
    cudaEventRecord(eB, sB);
    cudaStreamWaitEvent(0, eA, 0);
    cudaStreamWaitEvent(0, eB, 0);
}